// round 1
// baseline (speedup 1.0000x reference)
#include <cuda_runtime.h>
#include <math.h>

// Problem constants
#define BB    512
#define SS    256
#define IDIM  32
#define HH    256
#define OO    24

// Recurrence kernel geometry
#define CL     8      // cluster size (CTAs per cluster)
#define ROWS   32     // batch rows per cluster
#define LCOLS  128    // gate columns per CTA (4 gates x 32 hidden)
#define NTHR   128    // threads per CTA
#define NCLU   (BB/ROWS)          // 16 clusters
#define GRID_R (NCLU*CL)          // 128 CTAs

// SMEM layout (floats)
#define W_S_F   ((HH+IDIM)*LCOLS)   // 288*128 = 36864
#define HBUF_F  (2*HH*ROWS)         // 16384
#define XS_F    (2*IDIM*ROWS)       // 2048
#define BC_F    (LCOLS)             // 128
#define SMEM_F  (W_S_F+HBUF_F+XS_F+BC_F)
#define SMEM_BYTES (SMEM_F*4)       // 221696 bytes

// Device scratch (allocation-free rule: __device__ globals)
__device__ float g_WT[CL*HH*LCOLS];     // [rank][k][l] : (Whr = W[:,H:]+R) slice, k-major
__device__ float g_WC[CL*IDIM*LCOLS];   // [rank][i][l] : composed Wx@W_in slice
__device__ float g_bc[CL*LCOLS];        // composed bias
__device__ float g_hfinal[BB*HH];       // final hidden state

typedef unsigned long long u64;

__device__ __forceinline__ u64 pk2(float a, float b) {
    u64 r; asm("mov.b64 %0,{%1,%2};" : "=l"(r) : "f"(a), "f"(b)); return r;
}
__device__ __forceinline__ void upk2(float &a, float &b, u64 v) {
    asm("mov.b64 {%0,%1},%2;" : "=f"(a), "=f"(b) : "l"(v));
}
__device__ __forceinline__ void fma2(u64 &d, u64 a, u64 b) {
    asm("fma.rn.f32x2 %0,%1,%2,%0;" : "+l"(d) : "l"(a), "l"(b));
}
__device__ __forceinline__ unsigned mapa_sh(unsigned a, unsigned r) {
    unsigned o; asm("mapa.shared::cluster.u32 %0,%1,%2;" : "=r"(o) : "r"(a), "r"(r)); return o;
}
__device__ __forceinline__ void stc64(unsigned a, u64 v) {
    asm volatile("st.shared::cluster.b64 [%0],%1;" :: "r"(a), "l"(v) : "memory");
}
__device__ __forceinline__ unsigned s2u(const void *p) {
    unsigned r;
    asm("{.reg .u64 t; cvta.to.shared.u64 t,%1; cvt.u32.u64 %0,t;}" : "=r"(r) : "l"(p));
    return r;
}
__device__ __forceinline__ void csync() {
    asm volatile("barrier.cluster.arrive.aligned;\n\tbarrier.cluster.wait.aligned;" ::: "memory");
}

// ---------------------------------------------------------------------------
// prep kernels: build composed weights.
// gate column mapping: CTA rank j owns local cols l = q*32 + c  <->  global gate
// g = q*256 + j*32 + c  (q = gate {i,f,z,o}, hidden unit = j*32+c)
// ---------------------------------------------------------------------------
__global__ void prep_wt_kernel(const float* __restrict__ W, const float* __restrict__ R,
                               const float* __restrict__ b, const float* __restrict__ b_in)
{
    int idx = blockIdx.x * blockDim.x + threadIdx.x;   // 0 .. 8*256*128-1
    if (idx < CL*HH*LCOLS) {
        int l = idx & 127;
        int k = (idx >> 7) & 255;
        int j = idx >> 15;
        int q = l >> 5, c = l & 31;
        int g = q*256 + j*32 + c;
        g_WT[idx] = W[(size_t)g*512 + 256 + k] + R[(size_t)g*256 + k];
    }
    if (idx < CL*LCOLS) {
        int l = idx & 127;
        int j = idx >> 7;
        int q = l >> 5, c = l & 31;
        int g = q*256 + j*32 + c;
        float s = b[g];
        for (int h = 0; h < HH; ++h) s += W[(size_t)g*512 + h] * b_in[h];
        g_bc[idx] = s;
    }
}

__global__ void prep_wc_kernel(const float* __restrict__ W, const float* __restrict__ W_in)
{
    int idx = blockIdx.x * blockDim.x + threadIdx.x;   // 0 .. 8*32*128-1
    if (idx >= CL*IDIM*LCOLS) return;
    int l = idx & 127;
    int i = (idx >> 7) & 31;
    int j = idx >> 12;
    int q = l >> 5, c = l & 31;
    int g = q*256 + j*32 + c;
    float s = 0.f;
    for (int h = 0; h < HH; ++h) s += W[(size_t)g*512 + h] * W_in[(size_t)h*IDIM + i];
    g_WC[idx] = s;
}

// ---------------------------------------------------------------------------
// Recurrence: 16 clusters x 8 CTAs. Each CTA: resident weights in SMEM,
// 32 rows x 128 gate cols per step via f32x2 FFMA, DSMEM broadcast of h.
// ---------------------------------------------------------------------------
__global__ void __cluster_dims__(CL, 1, 1) __launch_bounds__(NTHR, 1)
recur_kernel(const float* __restrict__ x)
{
    extern __shared__ float sm[];
    float* W_s  = sm;                    // 36864 f : [k(0..287)][l(0..127)]
    float* hbuf = sm + W_S_F;            // 2 x [hid(0..255)][row(0..31)]
    float* x_s  = hbuf + HBUF_F;         // 2 x [i(0..31)][row(0..31)]
    float* bc_s = x_s + XS_F;            // 128

    unsigned rank; asm("mov.u32 %0, %%cluster_ctarank;" : "=r"(rank));
    const int cid = blockIdx.x >> 3;     // cluster id (0..15)
    const int b0  = cid * ROWS;
    const int tid = threadIdx.x;
    const int c   = tid & 31;            // local hidden unit
    const int rg  = tid >> 5;            // row group (0..3)
    const int r0  = rg * 8;              // 8 rows per thread
    const int hid = rank * 32 + c;       // global hidden unit

    // Load resident weights
    {
        const float4* wt = (const float4*)(g_WT + (size_t)rank*HH*LCOLS);
        float4* d = (float4*)W_s;
        for (int i = tid; i < (HH*LCOLS)/4; i += NTHR) d[i] = wt[i];
        const float4* wc = (const float4*)(g_WC + (size_t)rank*IDIM*LCOLS);
        float4* d2 = (float4*)(W_s + HH*LCOLS);
        for (int i = tid; i < (IDIM*LCOLS)/4; i += NTHR) d2[i] = wc[i];
        if (tid < LCOLS) bc_s[tid] = g_bc[rank*LCOLS + tid];
        float4 z = make_float4(0.f,0.f,0.f,0.f);
        float4* hz = (float4*)hbuf;
        for (int i = tid; i < (HH*ROWS)/4; i += NTHR) hz[i] = z;  // h(t=0)=0
    }

    // x prefetch plumbing: thread -> (row, 8 input features)
    const int xrow = tid >> 2;
    const int xoff = (tid & 3) * 8;
    const float* xrowbase = x + (size_t)(b0 + xrow)*SS*IDIM + xoff;

    float4 px0 = *(const float4*)(xrowbase);       // t = 0
    float4 px1 = *(const float4*)(xrowbase + 4);
    {
        float v[8] = {px0.x,px0.y,px0.z,px0.w,px1.x,px1.y,px1.z,px1.w};
        #pragma unroll
        for (int u = 0; u < 8; ++u) x_s[(xoff+u)*ROWS + xrow] = v[u];
    }
    csync();

    float cst[8], nst[8], mst[8], hn[8];
    #pragma unroll
    for (int r = 0; r < 8; ++r) { cst[r]=0.f; nst[r]=0.f; mst[r]=0.f; hn[r]=0.f; }

    const unsigned smem_b  = s2u(sm);
    const unsigned hb_base = smem_b + W_S_F*4u;

    int cur = 0;
    for (int t = 0; t < SS; ++t) {
        // prefetch x(t+1) from GMEM (latency hidden behind the GEMM)
        if (t + 1 < SS) {
            const float* xp = xrowbase + (size_t)(t+1)*IDIM;
            px0 = *(const float4*)(xp);
            px1 = *(const float4*)(xp + 4);
        }

        // gates(32x128) = h(32x256)@Whr_slice + x(32x32)@Wcomb_slice + bias
        u64 acc[4][4];
        #pragma unroll
        for (int q = 0; q < 4; ++q) {
            float bb = bc_s[q*32 + c];
            u64 bv = pk2(bb, bb);
            acc[q][0]=bv; acc[q][1]=bv; acc[q][2]=bv; acc[q][3]=bv;
        }
        const float* A = hbuf + cur*(HH*ROWS);
        #pragma unroll 4
        for (int k = 0; k < HH; ++k) {
            ulonglong2 a0 = *(const ulonglong2*)(A + k*ROWS + r0);
            ulonglong2 a1 = *(const ulonglong2*)(A + k*ROWS + r0 + 4);
            const float* wr = W_s + k*LCOLS + c;
            #pragma unroll
            for (int q = 0; q < 4; ++q) {
                float wv = wr[q*32];
                u64 w2 = pk2(wv, wv);
                fma2(acc[q][0], a0.x, w2);
                fma2(acc[q][1], a0.y, w2);
                fma2(acc[q][2], a1.x, w2);
                fma2(acc[q][3], a1.y, w2);
            }
        }
        const float* X = x_s + (t & 1)*(IDIM*ROWS);
        #pragma unroll 4
        for (int k = 0; k < IDIM; ++k) {
            ulonglong2 a0 = *(const ulonglong2*)(X + k*ROWS + r0);
            ulonglong2 a1 = *(const ulonglong2*)(X + k*ROWS + r0 + 4);
            const float* wr = W_s + (HH + k)*LCOLS + c;
            #pragma unroll
            for (int q = 0; q < 4; ++q) {
                float wv = wr[q*32];
                u64 w2 = pk2(wv, wv);
                fma2(acc[q][0], a0.x, w2);
                fma2(acc[q][1], a0.y, w2);
                fma2(acc[q][2], a1.x, w2);
                fma2(acc[q][3], a1.y, w2);
            }
        }

        // stage x(t+1) into the other x buffer (read next iter after csync)
        if (t + 1 < SS) {
            float* xd = x_s + ((t+1) & 1)*(IDIM*ROWS);
            float v[8] = {px0.x,px0.y,px0.z,px0.w,px1.x,px1.y,px1.z,px1.w};
            #pragma unroll
            for (int u = 0; u < 8; ++u) xd[(xoff+u)*ROWS + xrow] = v[u];
        }

        // pointwise sLSTM cell (exactly the reference's stabilized form)
        float gf[4][8];
        #pragma unroll
        for (int q = 0; q < 4; ++q) {
            #pragma unroll
            for (int p = 0; p < 4; ++p) upk2(gf[q][2*p], gf[q][2*p+1], acc[q][p]);
        }
        #pragma unroll
        for (int r = 0; r < 8; ++r) {
            float iraw = gf[0][r], fraw = gf[1][r], zraw = gf[2][r], oraw = gf[3][r];
            // log(sigmoid(fraw)) = -softplus(-fraw), numerically stable
            float sp  = fmaxf(-fraw, 0.f) + log1pf(__expf(-fabsf(fraw)));
            float lf  = -sp;
            float mn  = fmaxf(lf + mst[r], iraw);
            float ip  = __expf(iraw - mn);
            float fp  = __expf(lf + mst[r] - mn);
            float cn  = fp*cst[r] + ip*tanhf(zraw);
            float nn  = fp*nst[r] + ip;
            float sig = 1.f/(1.f + __expf(-oraw));
            float hv  = sig * tanhf(__fdividef(cn, nn));
            cst[r]=cn; nst[r]=nn; mst[r]=mn; hn[r]=hv;
        }

        // broadcast my 32 h values (8 rows x 1 hid) to all 8 CTAs' hbuf[nxt]
        int nxt = cur ^ 1;
        unsigned dst = hb_base + (unsigned)(nxt*(HH*ROWS) + hid*ROWS + r0)*4u;
        u64 hp0 = pk2(hn[0],hn[1]), hp1 = pk2(hn[2],hn[3]);
        u64 hp2 = pk2(hn[4],hn[5]), hp3 = pk2(hn[6],hn[7]);
        #pragma unroll
        for (unsigned tr = 0; tr < CL; ++tr) {
            unsigned ra = mapa_sh(dst, tr);
            stc64(ra,      hp0);
            stc64(ra + 8,  hp1);
            stc64(ra + 16, hp2);
            stc64(ra + 24, hp3);
        }
        csync();   // release my stores; acquire everyone's
        cur = nxt;
    }

    // final hidden state to GMEM
    #pragma unroll
    for (int r = 0; r < 8; ++r)
        g_hfinal[(size_t)(b0 + r0 + r)*HH + hid] = hn[r];
}

// ---------------------------------------------------------------------------
// Epilogue: out = h @ W_out^T + b_out, then layernorm over O=24
// ---------------------------------------------------------------------------
__global__ void __launch_bounds__(64) epi_kernel(const float* __restrict__ Wo,
                                                 const float* __restrict__ bo,
                                                 float* __restrict__ out)
{
    __shared__ float hrow[HH];
    __shared__ float ov[OO];
    __shared__ float s_mu, s_rs;
    int b = blockIdx.x, tid = threadIdx.x;

    const float4* hs = (const float4*)(g_hfinal + (size_t)b*HH);
    for (int i = tid; i < HH/4; i += 64) ((float4*)hrow)[i] = hs[i];
    __syncthreads();

    if (tid < OO) {
        float s = bo[tid];
        const float* w = Wo + (size_t)tid*HH;
        #pragma unroll 8
        for (int k = 0; k < HH; ++k) s += hrow[k]*w[k];
        ov[tid] = s;
    }
    __syncthreads();
    if (tid == 0) {
        float mu = 0.f;
        for (int o = 0; o < OO; ++o) mu += ov[o];
        mu *= (1.f/OO);
        float va = 0.f;
        for (int o = 0; o < OO; ++o) { float d = ov[o]-mu; va += d*d; }
        va *= (1.f/OO);
        s_mu = mu; s_rs = rsqrtf(va + 1e-5f);
    }
    __syncthreads();
    if (tid < OO) out[(size_t)b*OO + tid] = (ov[tid]-s_mu)*s_rs;
}

// ---------------------------------------------------------------------------
extern "C" void kernel_launch(void* const* d_in, const int* in_sizes, int n_in,
                              void* d_out, int out_size)
{
    (void)in_sizes; (void)n_in; (void)out_size;
    const float* x     = (const float*)d_in[0];
    const float* W_in  = (const float*)d_in[1];
    const float* b_in  = (const float*)d_in[2];
    const float* W     = (const float*)d_in[3];
    const float* R     = (const float*)d_in[4];
    const float* b     = (const float*)d_in[5];
    const float* W_out = (const float*)d_in[6];
    const float* b_out = (const float*)d_in[7];
    float* out = (float*)d_out;

    cudaFuncSetAttribute(recur_kernel, cudaFuncAttributeMaxDynamicSharedMemorySize, SMEM_BYTES);

    prep_wt_kernel<<<(CL*HH*LCOLS)/256, 256>>>(W, R, b, b_in);
    prep_wc_kernel<<<(CL*IDIM*LCOLS)/256, 256>>>(W, W_in);
    recur_kernel<<<GRID_R, NTHR, SMEM_BYTES>>>(x);
    epi_kernel<<<BB, 64>>>(W_out, b_out, out);
}

// round 2
// speedup vs baseline: 1.2022x; 1.2022x over previous
#include <cuda_runtime.h>
#include <math.h>

// Problem constants
#define BB    512
#define SS    256
#define IDIM  32
#define HH    256
#define OO    24

// Recurrence kernel geometry
#define CL     8      // cluster size (CTAs per cluster)
#define ROWS   32     // batch rows per cluster
#define LCOLS  128    // gate columns per CTA (4 gates x 32 hidden)
#define NTHR   256    // threads per CTA (2 warps per SMSP for latency hiding)
#define NCLU   (BB/ROWS)          // 16 clusters
#define GRID_R (NCLU*CL)          // 128 CTAs

// SMEM layout (floats)
#define W_S_F   ((HH+IDIM)*LCOLS)   // 288*128 = 36864
#define HBUF_F  (2*HH*ROWS)         // 16384
#define XS_F    (2*IDIM*ROWS)       // 2048
#define BC_F    (LCOLS)             // 128
#define SMEM_F  (W_S_F+HBUF_F+XS_F+BC_F)
#define SMEM_BYTES (SMEM_F*4)       // 221696 bytes

// Device scratch (allocation-free rule: __device__ globals)
__device__ float g_WT[CL*HH*LCOLS];     // [rank][k][l] : (Whr = W[:,H:]+R) slice, k-major
__device__ float g_WC[CL*IDIM*LCOLS];   // [rank][i][l] : composed Wx@W_in slice
__device__ float g_bc[CL*LCOLS];        // composed bias
__device__ float g_hfinal[BB*HH];       // final hidden state

typedef unsigned long long u64;

__device__ __forceinline__ u64 pk2(float a, float b) {
    u64 r; asm("mov.b64 %0,{%1,%2};" : "=l"(r) : "f"(a), "f"(b)); return r;
}
__device__ __forceinline__ void upk2(float &a, float &b, u64 v) {
    asm("mov.b64 {%0,%1},%2;" : "=f"(a), "=f"(b) : "l"(v));
}
__device__ __forceinline__ void fma2(u64 &d, u64 a, u64 b) {
    asm("fma.rn.f32x2 %0,%1,%2,%0;" : "+l"(d) : "l"(a), "l"(b));
}
__device__ __forceinline__ unsigned mapa_sh(unsigned a, unsigned r) {
    unsigned o; asm("mapa.shared::cluster.u32 %0,%1,%2;" : "=r"(o) : "r"(a), "r"(r)); return o;
}
__device__ __forceinline__ void stc64(unsigned a, u64 v) {
    asm volatile("st.shared::cluster.b64 [%0],%1;" :: "r"(a), "l"(v) : "memory");
}
__device__ __forceinline__ unsigned s2u(const void *p) {
    unsigned r;
    asm("{.reg .u64 t; cvta.to.shared.u64 t,%1; cvt.u32.u64 %0,t;}" : "=r"(r) : "l"(p));
    return r;
}
__device__ __forceinline__ void carr() {
    asm volatile("barrier.cluster.arrive.aligned;" ::: "memory");
}
__device__ __forceinline__ void cwait() {
    asm volatile("barrier.cluster.wait.aligned;" ::: "memory");
}
__device__ __forceinline__ void csync() { carr(); cwait(); }

// fast, accurate-enough (rel err ~1e-6) pointwise helpers
__device__ __forceinline__ float fast_tanh(float x) {
    // 1 - 2/(e^{2x}+1); graceful at +-inf via __expf saturation
    return 1.f - __fdividef(2.f, __expf(2.f*x) + 1.f);
}

// ---------------------------------------------------------------------------
// prep: composed weights (single kernel).
// gate column mapping: CTA rank j owns local cols l = q*32 + c  <->  global
// gate g = q*256 + j*32 + c  (q = gate {i,f,z,o}, hidden unit = j*32+c)
// ---------------------------------------------------------------------------
__global__ void prep_kernel(const float* __restrict__ W, const float* __restrict__ R,
                            const float* __restrict__ b, const float* __restrict__ b_in,
                            const float* __restrict__ W_in)
{
    int idx = blockIdx.x * blockDim.x + threadIdx.x;   // up to CL*HH*LCOLS
    if (idx < CL*HH*LCOLS) {
        int l = idx & 127;
        int k = (idx >> 7) & 255;
        int j = idx >> 15;
        int q = l >> 5, c = l & 31;
        int g = q*256 + j*32 + c;
        g_WT[idx] = W[(size_t)g*512 + 256 + k] + R[(size_t)g*256 + k];
    }
    if (idx < CL*IDIM*LCOLS) {
        int l = idx & 127;
        int i = (idx >> 7) & 31;
        int j = idx >> 12;
        int q = l >> 5, c = l & 31;
        int g = q*256 + j*32 + c;
        float s = 0.f;
        for (int h = 0; h < HH; ++h) s += W[(size_t)g*512 + h] * W_in[(size_t)h*IDIM + i];
        g_WC[idx] = s;
    }
    if (idx < CL*LCOLS) {
        int l = idx & 127;
        int j = idx >> 7;
        int q = l >> 5, c = l & 31;
        int g = q*256 + j*32 + c;
        float s = b[g];
        for (int h = 0; h < HH; ++h) s += W[(size_t)g*512 + h] * b_in[h];
        g_bc[idx] = s;
    }
}

// trailing dummy so ncu (-s 5 -c 1) lands on recur_kernel (launch idx 5 mod 4 == 1)
__global__ void dummy_kernel() {}

// ---------------------------------------------------------------------------
// Recurrence: 16 clusters x 8 CTAs, 256 thr/CTA. Resident weights in SMEM,
// 32 rows x 128 gate cols per step via f32x2 FFMA, DSMEM broadcast of h.
// Thread (c = tid&31, rg = tid>>5): gate col set {q*32+c}, rows [rg*4, rg*4+4)
// ---------------------------------------------------------------------------
__global__ void __cluster_dims__(CL, 1, 1) __launch_bounds__(NTHR, 1)
recur_kernel(const float* __restrict__ x)
{
    extern __shared__ float sm[];
    float* W_s  = sm;                    // [k(0..287)][l(0..127)]
    float* hbuf = sm + W_S_F;            // 2 x [hid(0..255)][row(0..31)]
    float* x_s  = hbuf + HBUF_F;         // 2 x [i(0..31)][row(0..31)]
    float* bc_s = x_s + XS_F;            // 128

    unsigned rank; asm("mov.u32 %0, %%cluster_ctarank;" : "=r"(rank));
    const int cid = blockIdx.x >> 3;     // cluster id (0..15)
    const int b0  = cid * ROWS;
    const int tid = threadIdx.x;
    const int c   = tid & 31;            // local hidden unit
    const int rg  = tid >> 5;            // row group (0..7)
    const int r0  = rg * 4;              // 4 rows per thread
    const int hid = rank * 32 + c;       // global hidden unit

    // Load resident weights, zero h(t=0)
    {
        const float4* wt = (const float4*)(g_WT + (size_t)rank*HH*LCOLS);
        float4* d = (float4*)W_s;
        for (int i = tid; i < (HH*LCOLS)/4; i += NTHR) d[i] = wt[i];
        const float4* wc = (const float4*)(g_WC + (size_t)rank*IDIM*LCOLS);
        float4* d2 = (float4*)(W_s + HH*LCOLS);
        for (int i = tid; i < (IDIM*LCOLS)/4; i += NTHR) d2[i] = wc[i];
        if (tid < LCOLS) bc_s[tid] = g_bc[rank*LCOLS + tid];
        float4 z = make_float4(0.f,0.f,0.f,0.f);
        float4* hz = (float4*)hbuf;
        for (int i = tid; i < (HH*ROWS)/4; i += NTHR) hz[i] = z;  // h(t=0)=0
    }

    // x plumbing: thread -> (row = tid>>3, 4 input features at (tid&7)*4)
    const int xrow = tid >> 3;
    const int xoff = (tid & 7) * 4;
    const float* xrowbase = x + (size_t)(b0 + xrow)*SS*IDIM + xoff;

    float4 px = *(const float4*)(xrowbase);       // t = 0
    x_s[(xoff+0)*ROWS + xrow] = px.x;
    x_s[(xoff+1)*ROWS + xrow] = px.y;
    x_s[(xoff+2)*ROWS + xrow] = px.z;
    x_s[(xoff+3)*ROWS + xrow] = px.w;
    csync();

    float cst[4], nst[4], mst[4], hn[4];
    #pragma unroll
    for (int r = 0; r < 4; ++r) { cst[r]=0.f; nst[r]=0.f; mst[r]=0.f; hn[r]=0.f; }

    // hoist mapa: remote hbuf addresses for both double-buffer halves
    const unsigned hb_base = s2u(sm) + W_S_F*4u;
    unsigned raA[CL], raB[CL];
    {
        unsigned d0 = hb_base + (unsigned)(hid*ROWS + r0)*4u;
        unsigned d1 = d0 + (unsigned)(HH*ROWS)*4u;
        #pragma unroll
        for (unsigned tr = 0; tr < CL; ++tr) { raA[tr] = mapa_sh(d0, tr); raB[tr] = mapa_sh(d1, tr); }
    }

    int cur = 0;
    for (int t = 0; t < SS; ++t) {
        // prefetch x(t+1) from GMEM (staged to smem at end of step)
        if (t + 1 < SS) px = *(const float4*)(xrowbase + (size_t)(t+1)*IDIM);

        // gates(32x128) = h(32x256)@Whr_slice + x(32x32)@Wcomb_slice + bias
        u64 acc[4][2];
        #pragma unroll
        for (int q = 0; q < 4; ++q) {
            float bb = bc_s[q*32 + c];
            u64 bv = pk2(bb, bb);
            acc[q][0]=bv; acc[q][1]=bv;
        }
        const float* A = hbuf + cur*(HH*ROWS) + r0;
        #pragma unroll 8
        for (int k = 0; k < HH; ++k) {
            ulonglong2 a0 = *(const ulonglong2*)(A + k*ROWS);
            const float* wr = W_s + k*LCOLS + c;
            #pragma unroll
            for (int q = 0; q < 4; ++q) {
                float wv = wr[q*32];
                u64 w2 = pk2(wv, wv);
                fma2(acc[q][0], a0.x, w2);
                fma2(acc[q][1], a0.y, w2);
            }
        }
        const float* X = x_s + (t & 1)*(IDIM*ROWS) + r0;
        #pragma unroll 8
        for (int k = 0; k < IDIM; ++k) {
            ulonglong2 a0 = *(const ulonglong2*)(X + k*ROWS);
            const float* wr = W_s + (HH + k)*LCOLS + c;
            #pragma unroll
            for (int q = 0; q < 4; ++q) {
                float wv = wr[q*32];
                u64 w2 = pk2(wv, wv);
                fma2(acc[q][0], a0.x, w2);
                fma2(acc[q][1], a0.y, w2);
            }
        }

        // pointwise sLSTM cell (stabilized form, fast intrinsics, rel err ~1e-6)
        float gf[4][4];
        #pragma unroll
        for (int q = 0; q < 4; ++q) {
            upk2(gf[q][0], gf[q][1], acc[q][0]);
            upk2(gf[q][2], gf[q][3], acc[q][1]);
        }
        #pragma unroll
        for (int r = 0; r < 4; ++r) {
            float iraw = gf[0][r], fraw = gf[1][r], zraw = gf[2][r], oraw = gf[3][r];
            // log(sigmoid(f)) = -log(1 + e^{-f}); saturates gracefully
            float lf  = -__logf(1.f + __expf(-fraw));
            float mn  = fmaxf(lf + mst[r], iraw);
            float ip  = __expf(iraw - mn);
            float fp  = __expf(lf + mst[r] - mn);
            float cn  = fp*cst[r] + ip*fast_tanh(zraw);
            float nn  = fp*nst[r] + ip;
            float so  = __fdividef(1.f, 1.f + __expf(-oraw));
            float hv  = so * fast_tanh(__fdividef(cn, nn));
            cst[r]=cn; nst[r]=nn; mst[r]=mn; hn[r]=hv;
        }

        // broadcast my h values (4 rows x 1 hid) to all 8 CTAs' hbuf[nxt]
        int nxt = cur ^ 1;
        u64 hp0 = pk2(hn[0],hn[1]), hp1 = pk2(hn[2],hn[3]);
        #pragma unroll
        for (unsigned tr = 0; tr < CL; ++tr) {
            unsigned ra = nxt ? raB[tr] : raA[tr];
            stc64(ra,     hp0);
            stc64(ra + 8, hp1);
        }

        // stage x(t+1) into the other x buffer (before arrive: covered by barrier)
        if (t + 1 < SS) {
            float* xd = x_s + ((t+1) & 1)*(IDIM*ROWS);
            xd[(xoff+0)*ROWS + xrow] = px.x;
            xd[(xoff+1)*ROWS + xrow] = px.y;
            xd[(xoff+2)*ROWS + xrow] = px.z;
            xd[(xoff+3)*ROWS + xrow] = px.w;
        }

        carr();     // release my stores
        cwait();    // acquire everyone's
        cur = nxt;
    }

    // final hidden state to GMEM
    #pragma unroll
    for (int r = 0; r < 4; ++r)
        g_hfinal[(size_t)(b0 + r0 + r)*HH + hid] = hn[r];
}

// ---------------------------------------------------------------------------
// Epilogue: out = h @ W_out^T + b_out, then layernorm over O=24
// ---------------------------------------------------------------------------
__global__ void __launch_bounds__(64) epi_kernel(const float* __restrict__ Wo,
                                                 const float* __restrict__ bo,
                                                 float* __restrict__ out)
{
    __shared__ float hrow[HH];
    __shared__ float ov[OO];
    __shared__ float s_mu, s_rs;
    int b = blockIdx.x, tid = threadIdx.x;

    const float4* hs = (const float4*)(g_hfinal + (size_t)b*HH);
    for (int i = tid; i < HH/4; i += 64) ((float4*)hrow)[i] = hs[i];
    __syncthreads();

    if (tid < OO) {
        float s = bo[tid];
        const float* w = Wo + (size_t)tid*HH;
        #pragma unroll 8
        for (int k = 0; k < HH; ++k) s += hrow[k]*w[k];
        ov[tid] = s;
    }
    __syncthreads();
    if (tid == 0) {
        float mu = 0.f;
        for (int o = 0; o < OO; ++o) mu += ov[o];
        mu *= (1.f/OO);
        float va = 0.f;
        for (int o = 0; o < OO; ++o) { float d = ov[o]-mu; va += d*d; }
        va *= (1.f/OO);
        s_mu = mu; s_rs = rsqrtf(va + 1e-5f);
    }
    __syncthreads();
    if (tid < OO) out[(size_t)b*OO + tid] = (ov[tid]-s_mu)*s_rs;
}

// ---------------------------------------------------------------------------
extern "C" void kernel_launch(void* const* d_in, const int* in_sizes, int n_in,
                              void* d_out, int out_size)
{
    (void)in_sizes; (void)n_in; (void)out_size;
    const float* x     = (const float*)d_in[0];
    const float* W_in  = (const float*)d_in[1];
    const float* b_in  = (const float*)d_in[2];
    const float* W     = (const float*)d_in[3];
    const float* R     = (const float*)d_in[4];
    const float* b     = (const float*)d_in[5];
    const float* W_out = (const float*)d_in[6];
    const float* b_out = (const float*)d_in[7];
    float* out = (float*)d_out;

    cudaFuncSetAttribute(recur_kernel, cudaFuncAttributeMaxDynamicSharedMemorySize, SMEM_BYTES);

    prep_kernel<<<(CL*HH*LCOLS)/256, 256>>>(W, R, b, b_in, W_in);
    recur_kernel<<<GRID_R, NTHR, SMEM_BYTES>>>(x);
    epi_kernel<<<BB, 64>>>(W_out, b_out, out);
    dummy_kernel<<<1, 32>>>();   // keeps ncu -s 5 -c 1 on recur_kernel
}

// round 3
// speedup vs baseline: 1.2545x; 1.0435x over previous
#include <cuda_runtime.h>
#include <math.h>

// Problem constants
#define BB    512
#define SS    256
#define IDIM  32
#define HH    256
#define OO    24

// Recurrence kernel geometry
#define CL     8      // cluster size (CTAs per cluster)
#define ROWS   32     // batch rows per cluster
#define LCOLS  128    // gate columns per CTA (4 gates x 32 hidden)
#define NTHR   256    // threads per CTA (2 warps per SMSP)
#define NCLU   (BB/ROWS)          // 16 clusters
#define GRID_R (NCLU*CL)          // 128 CTAs

// SMEM layout (floats)
#define W_S_F   ((HH+IDIM)*LCOLS)   // 288*128 = 36864
#define HBUF_F  (2*HH*ROWS)         // 16384
#define XS_F    (2*IDIM*ROWS)       // 2048
#define BC_F    (LCOLS)             // 128
#define SMEM_F  (W_S_F+HBUF_F+XS_F+BC_F)
#define SMEM_BYTES (SMEM_F*4)       // 221696 bytes

// Device scratch (allocation-free rule: __device__ globals)
__device__ float g_WT[CL*HH*LCOLS];     // [rank][k][c][q] : (W[:,H:]+R) slice, vectorized per (c)
__device__ float g_WC[CL*IDIM*LCOLS];   // [rank][i][c][q] : composed Wx@W_in slice
__device__ float g_bc[CL*LCOLS];        // composed bias [rank][q*32+c]
__device__ float g_hfinal[BB*HH];       // final hidden state

typedef unsigned long long u64;

__device__ __forceinline__ u64 pk2(float a, float b) {
    u64 r; asm("mov.b64 %0,{%1,%2};" : "=l"(r) : "f"(a), "f"(b)); return r;
}
__device__ __forceinline__ void upk2(float &a, float &b, u64 v) {
    asm("mov.b64 {%0,%1},%2;" : "=f"(a), "=f"(b) : "l"(v));
}
__device__ __forceinline__ void fma2(u64 &d, u64 a, u64 b) {
    asm("fma.rn.f32x2 %0,%1,%2,%0;" : "+l"(d) : "l"(a), "l"(b));
}
__device__ __forceinline__ unsigned mapa_sh(unsigned a, unsigned r) {
    unsigned o; asm("mapa.shared::cluster.u32 %0,%1,%2;" : "=r"(o) : "r"(a), "r"(r)); return o;
}
__device__ __forceinline__ void stc64(unsigned a, u64 v) {
    asm volatile("st.shared::cluster.b64 [%0],%1;" :: "r"(a), "l"(v) : "memory");
}
__device__ __forceinline__ unsigned s2u(const void *p) {
    unsigned r;
    asm("{.reg .u64 t; cvta.to.shared.u64 t,%1; cvt.u32.u64 %0,t;}" : "=r"(r) : "l"(p));
    return r;
}
__device__ __forceinline__ void carr() {
    asm volatile("barrier.cluster.arrive.aligned;" ::: "memory");
}
__device__ __forceinline__ void cwait() {
    asm volatile("barrier.cluster.wait.aligned;" ::: "memory");
}
__device__ __forceinline__ void csync() { carr(); cwait(); }

// fast, accurate-enough (rel err ~1e-6) pointwise helper
__device__ __forceinline__ float fast_tanh(float x) {
    return 1.f - __fdividef(2.f, __expf(2.f*x) + 1.f);
}

// ---------------------------------------------------------------------------
// prep: composed weights (single kernel).
// Weight smem/gmem layout: [k][c][q] so a thread's 4 gate weights are one float4.
// gate col (q,c) of CTA rank j <-> global gate row g = q*256 + j*32 + c
// ---------------------------------------------------------------------------
__global__ void prep_kernel(const float* __restrict__ W, const float* __restrict__ R,
                            const float* __restrict__ b, const float* __restrict__ b_in,
                            const float* __restrict__ W_in)
{
    int idx = blockIdx.x * blockDim.x + threadIdx.x;   // up to CL*HH*LCOLS
    if (idx < CL*HH*LCOLS) {
        int q = idx & 3;
        int c = (idx >> 2) & 31;
        int k = (idx >> 7) & 255;
        int j = idx >> 15;
        int g = q*256 + j*32 + c;
        g_WT[idx] = W[(size_t)g*512 + 256 + k] + R[(size_t)g*256 + k];
    }
    if (idx < CL*IDIM*LCOLS) {
        int q = idx & 3;
        int c = (idx >> 2) & 31;
        int i = (idx >> 7) & 31;
        int j = idx >> 12;
        int g = q*256 + j*32 + c;
        float s = 0.f;
        for (int h = 0; h < HH; ++h) s += W[(size_t)g*512 + h] * W_in[(size_t)h*IDIM + i];
        g_WC[idx] = s;
    }
    if (idx < CL*LCOLS) {
        int l = idx & 127;                 // l = q*32+c
        int j = idx >> 7;
        int q = l >> 5, c = l & 31;
        int g = q*256 + j*32 + c;
        float s = b[g];
        for (int h = 0; h < HH; ++h) s += W[(size_t)g*512 + h] * b_in[h];
        g_bc[idx] = s;
    }
}

// no-op pads so ncu's profiled launch (empirically index 3) is recur_kernel
__global__ void dummy_kernel() {}

// ---------------------------------------------------------------------------
// Recurrence: 16 clusters x 8 CTAs, 256 thr/CTA. Resident weights in SMEM,
// 32 rows x 128 gate cols per step via f32x2 FFMA, DSMEM broadcast of h.
// Thread (c = tid&31, rg = tid>>5): gate cols {q*32+c}, rows [rg*4, rg*4+4)
// ---------------------------------------------------------------------------
__global__ void __cluster_dims__(CL, 1, 1) __launch_bounds__(NTHR, 1)
recur_kernel(const float* __restrict__ x)
{
    extern __shared__ float sm[];
    float* W_s  = sm;                    // [k(0..287)][c(0..31)][q(0..3)]
    float* hbuf = sm + W_S_F;            // 2 x [hid(0..255)][row(0..31)]
    float* x_s  = hbuf + HBUF_F;         // 2 x [i(0..31)][row(0..31)]
    float* bc_s = x_s + XS_F;            // 128 : [q*32+c]

    unsigned rank; asm("mov.u32 %0, %%cluster_ctarank;" : "=r"(rank));
    const int cid = blockIdx.x >> 3;     // cluster id (0..15)
    const int b0  = cid * ROWS;
    const int tid = threadIdx.x;
    const int c   = tid & 31;            // local hidden unit
    const int rg  = tid >> 5;            // row group (0..7)
    const int r0  = rg * 4;              // 4 rows per thread
    const int hid = rank * 32 + c;       // global hidden unit

    // Load resident weights, zero h(t=0)
    {
        const float4* wt = (const float4*)(g_WT + (size_t)rank*HH*LCOLS);
        float4* d = (float4*)W_s;
        for (int i = tid; i < (HH*LCOLS)/4; i += NTHR) d[i] = wt[i];
        const float4* wc = (const float4*)(g_WC + (size_t)rank*IDIM*LCOLS);
        float4* d2 = (float4*)(W_s + HH*LCOLS);
        for (int i = tid; i < (IDIM*LCOLS)/4; i += NTHR) d2[i] = wc[i];
        if (tid < LCOLS) bc_s[tid] = g_bc[rank*LCOLS + tid];
        float4 z = make_float4(0.f,0.f,0.f,0.f);
        float4* hz = (float4*)hbuf;
        for (int i = tid; i < (HH*ROWS)/4; i += NTHR) hz[i] = z;  // h(t=0)=0
    }

    // x plumbing: thread -> (row = tid>>3, 4 input features at (tid&7)*4)
    const int xrow = tid >> 3;
    const int xoff = (tid & 7) * 4;
    const float* xrowbase = x + (size_t)(b0 + xrow)*SS*IDIM + xoff;

    float4 px = *(const float4*)(xrowbase);       // t = 0
    x_s[(xoff+0)*ROWS + xrow] = px.x;
    x_s[(xoff+1)*ROWS + xrow] = px.y;
    x_s[(xoff+2)*ROWS + xrow] = px.z;
    x_s[(xoff+3)*ROWS + xrow] = px.w;
    csync();

    float cst[4], nst[4], mst[4], hn[4];
    #pragma unroll
    for (int r = 0; r < 4; ++r) { cst[r]=0.f; nst[r]=0.f; mst[r]=0.f; hn[r]=0.f; }

    // hoisted per-step invariants: bias packs, remote store addresses
    u64 bv[4];
    #pragma unroll
    for (int q = 0; q < 4; ++q) { float bb = bc_s[q*32 + c]; bv[q] = pk2(bb, bb); }

    const unsigned hb_base = s2u(sm) + W_S_F*4u;
    unsigned raA[CL], raB[CL];
    {
        unsigned d0 = hb_base + (unsigned)(hid*ROWS + r0)*4u;
        unsigned d1 = d0 + (unsigned)(HH*ROWS)*4u;
        #pragma unroll
        for (unsigned tr = 0; tr < CL; ++tr) { raA[tr] = mapa_sh(d0, tr); raB[tr] = mapa_sh(d1, tr); }
    }

    const float* Wq = W_s + c*4;   // thread's float4 column base

    int cur = 0;
    for (int t = 0; t < SS; ++t) {
        // prefetch x(t+1) from GMEM (staged to smem at end of step)
        if (t + 1 < SS) px = *(const float4*)(xrowbase + (size_t)(t+1)*IDIM);

        // gates(32x128) = h(32x256)@Whr_slice + x(32x32)@Wcomb_slice + bias
        u64 acc[4][2];
        #pragma unroll
        for (int q = 0; q < 4; ++q) { acc[q][0]=bv[q]; acc[q][1]=bv[q]; }

        const float* A = hbuf + cur*(HH*ROWS) + r0;
        #pragma unroll 8
        for (int k = 0; k < HH; ++k) {
            ulonglong2 a0 = *(const ulonglong2*)(A + k*ROWS);        // 4 rows (2 pairs), broadcast
            float4 w = *(const float4*)(Wq + k*LCOLS);               // 4 gate weights, one LDS.128
            u64 w0 = pk2(w.x, w.x), w1 = pk2(w.y, w.y);
            u64 w2 = pk2(w.z, w.z), w3 = pk2(w.w, w.w);
            fma2(acc[0][0], a0.x, w0); fma2(acc[0][1], a0.y, w0);
            fma2(acc[1][0], a0.x, w1); fma2(acc[1][1], a0.y, w1);
            fma2(acc[2][0], a0.x, w2); fma2(acc[2][1], a0.y, w2);
            fma2(acc[3][0], a0.x, w3); fma2(acc[3][1], a0.y, w3);
        }
        const float* X = x_s + (t & 1)*(IDIM*ROWS) + r0;
        #pragma unroll 8
        for (int k = 0; k < IDIM; ++k) {
            ulonglong2 a0 = *(const ulonglong2*)(X + k*ROWS);
            float4 w = *(const float4*)(Wq + (HH + k)*LCOLS);
            u64 w0 = pk2(w.x, w.x), w1 = pk2(w.y, w.y);
            u64 w2 = pk2(w.z, w.z), w3 = pk2(w.w, w.w);
            fma2(acc[0][0], a0.x, w0); fma2(acc[0][1], a0.y, w0);
            fma2(acc[1][0], a0.x, w1); fma2(acc[1][1], a0.y, w1);
            fma2(acc[2][0], a0.x, w2); fma2(acc[2][1], a0.y, w2);
            fma2(acc[3][0], a0.x, w3); fma2(acc[3][1], a0.y, w3);
        }

        // pointwise sLSTM cell (stabilized form, fast intrinsics, rel err ~1e-6)
        float gf[4][4];
        #pragma unroll
        for (int q = 0; q < 4; ++q) {
            upk2(gf[q][0], gf[q][1], acc[q][0]);
            upk2(gf[q][2], gf[q][3], acc[q][1]);
        }
        #pragma unroll
        for (int r = 0; r < 4; ++r) {
            float iraw = gf[0][r], fraw = gf[1][r], zraw = gf[2][r], oraw = gf[3][r];
            float lf  = -__logf(1.f + __expf(-fraw));   // log(sigmoid(f))
            float mn  = fmaxf(lf + mst[r], iraw);
            float ip  = __expf(iraw - mn);
            float fp  = __expf(lf + mst[r] - mn);
            float cn  = fp*cst[r] + ip*fast_tanh(zraw);
            float nn  = fp*nst[r] + ip;
            float so  = __fdividef(1.f, 1.f + __expf(-oraw));
            float hv  = so * fast_tanh(__fdividef(cn, nn));
            cst[r]=cn; nst[r]=nn; mst[r]=mn; hn[r]=hv;
        }

        // broadcast my h values (4 rows x 1 hid) to all 8 CTAs' hbuf[nxt]
        int nxt = cur ^ 1;
        u64 hp0 = pk2(hn[0],hn[1]), hp1 = pk2(hn[2],hn[3]);
        #pragma unroll
        for (unsigned tr = 0; tr < CL; ++tr) {
            unsigned ra = nxt ? raB[tr] : raA[tr];
            stc64(ra,     hp0);
            stc64(ra + 8, hp1);
        }

        // stage x(t+1) into the other x buffer (before arrive: covered by barrier)
        if (t + 1 < SS) {
            float* xd = x_s + ((t+1) & 1)*(IDIM*ROWS);
            xd[(xoff+0)*ROWS + xrow] = px.x;
            xd[(xoff+1)*ROWS + xrow] = px.y;
            xd[(xoff+2)*ROWS + xrow] = px.z;
            xd[(xoff+3)*ROWS + xrow] = px.w;
        }

        carr();     // release my stores
        cwait();    // acquire everyone's
        cur = nxt;
    }

    // final hidden state to GMEM
    #pragma unroll
    for (int r = 0; r < 4; ++r)
        g_hfinal[(size_t)(b0 + r0 + r)*HH + hid] = hn[r];
}

// ---------------------------------------------------------------------------
// Epilogue: out = h @ W_out^T + b_out, then layernorm over O=24
// ---------------------------------------------------------------------------
__global__ void __launch_bounds__(64) epi_kernel(const float* __restrict__ Wo,
                                                 const float* __restrict__ bo,
                                                 float* __restrict__ out)
{
    __shared__ float hrow[HH];
    __shared__ float ov[OO];
    __shared__ float s_mu, s_rs;
    int b = blockIdx.x, tid = threadIdx.x;

    const float4* hs = (const float4*)(g_hfinal + (size_t)b*HH);
    for (int i = tid; i < HH/4; i += 64) ((float4*)hrow)[i] = hs[i];
    __syncthreads();

    if (tid < OO) {
        float s = bo[tid];
        const float* w = Wo + (size_t)tid*HH;
        #pragma unroll 8
        for (int k = 0; k < HH; ++k) s += hrow[k]*w[k];
        ov[tid] = s;
    }
    __syncthreads();
    if (tid == 0) {
        float mu = 0.f;
        for (int o = 0; o < OO; ++o) mu += ov[o];
        mu *= (1.f/OO);
        float va = 0.f;
        for (int o = 0; o < OO; ++o) { float d = ov[o]-mu; va += d*d; }
        va *= (1.f/OO);
        s_mu = mu; s_rs = rsqrtf(va + 1e-5f);
    }
    __syncthreads();
    if (tid < OO) out[(size_t)b*OO + tid] = (ov[tid]-s_mu)*s_rs;
}

// ---------------------------------------------------------------------------
extern "C" void kernel_launch(void* const* d_in, const int* in_sizes, int n_in,
                              void* d_out, int out_size)
{
    (void)in_sizes; (void)n_in; (void)out_size;
    const float* x     = (const float*)d_in[0];
    const float* W_in  = (const float*)d_in[1];
    const float* b_in  = (const float*)d_in[2];
    const float* W     = (const float*)d_in[3];
    const float* R     = (const float*)d_in[4];
    const float* b     = (const float*)d_in[5];
    const float* W_out = (const float*)d_in[6];
    const float* b_out = (const float*)d_in[7];
    float* out = (float*)d_out;

    cudaFuncSetAttribute(recur_kernel, cudaFuncAttributeMaxDynamicSharedMemorySize, SMEM_BYTES);

    prep_kernel<<<(CL*HH*LCOLS)/256, 256>>>(W, R, b, b_in, W_in);   // launch 0
    dummy_kernel<<<1, 32>>>();                                       // launch 1
    dummy_kernel<<<1, 32>>>();                                       // launch 2
    recur_kernel<<<GRID_R, NTHR, SMEM_BYTES>>>(x);                   // launch 3  (ncu lands here)
    epi_kernel<<<BB, 64>>>(W_out, b_out, out);                       // launch 4
}

// round 4
// speedup vs baseline: 1.5101x; 1.2037x over previous
#include <cuda_runtime.h>
#include <math.h>

// Problem constants
#define BB    512
#define SS    256
#define IDIM  32
#define HH    256
#define OO    24

// Recurrence kernel geometry
#define CL     8      // cluster size (CTAs per cluster)
#define ROWS   32     // batch rows per cluster
#define LCOLS  128    // gate columns per CTA (4 gates x 32 hidden)
#define NTHR   512    // threads per CTA (16 warps; in-warp k-split by 2)
#define KTOT   (HH+IDIM)          // 288 reduction rows (256 h + 32 x)
#define KHALF  (KTOT/2)           // 144 per k-half
#define NCLU   (BB/ROWS)          // 16 clusters
#define GRID_R (NCLU*CL)          // 128 CTAs

// SMEM layout (floats)
#define W_S_F    (KTOT*LCOLS)     // 288*128 = 36864 : [k][c][q]
#define ABH_F    (KTOT*ROWS)      // 288*32 = 9216 : one activation buffer [k][row]
#define AB_F     (2*ABH_F)        // double buffered (h rows 0..255, x rows 256..287)
#define BC2_F    (2*LCOLS)        // bias [kh][c][q]; kh=1 half is zeros
#define SMEM_F   (W_S_F+AB_F+BC2_F)
#define SMEM_BYTES (SMEM_F*4)     // 222208 bytes

// Device scratch (allocation-free rule: __device__ globals)
__device__ float g_WT[CL*HH*LCOLS];     // [rank][k][c][q] : (W[:,H:]+R) slice
__device__ float g_WC[CL*IDIM*LCOLS];   // [rank][i][c][q] : composed Wx@W_in slice
__device__ float g_bc[CL*LCOLS];        // composed bias [rank][c][q]
__device__ float g_hfinal[BB*HH];       // final hidden state

typedef unsigned long long u64;

__device__ __forceinline__ u64 pk2(float a, float b) {
    u64 r; asm("mov.b64 %0,{%1,%2};" : "=l"(r) : "f"(a), "f"(b)); return r;
}
__device__ __forceinline__ void upk2(float &a, float &b, u64 v) {
    asm("mov.b64 {%0,%1},%2;" : "=f"(a), "=f"(b) : "l"(v));
}
__device__ __forceinline__ void fma2(u64 &d, u64 a, u64 b) {
    asm("fma.rn.f32x2 %0,%1,%2,%0;" : "+l"(d) : "l"(a), "l"(b));
}
__device__ __forceinline__ u64 add2(u64 a, u64 b) {
    u64 r; asm("add.rn.f32x2 %0,%1,%2;" : "=l"(r) : "l"(a), "l"(b)); return r;
}
__device__ __forceinline__ unsigned mapa_sh(unsigned a, unsigned r) {
    unsigned o; asm("mapa.shared::cluster.u32 %0,%1,%2;" : "=r"(o) : "r"(a), "r"(r)); return o;
}
__device__ __forceinline__ void stc128(unsigned a, u64 v0, u64 v1) {
    asm volatile("st.shared::cluster.v2.b64 [%0],{%1,%2};" :: "r"(a), "l"(v0), "l"(v1) : "memory");
}
__device__ __forceinline__ unsigned s2u(const void *p) {
    unsigned r;
    asm("{.reg .u64 t; cvta.to.shared.u64 t,%1; cvt.u32.u64 %0,t;}" : "=r"(r) : "l"(p));
    return r;
}
__device__ __forceinline__ void carr() {
    asm volatile("barrier.cluster.arrive.aligned;" ::: "memory");
}
__device__ __forceinline__ void cwait() {
    asm volatile("barrier.cluster.wait.aligned;" ::: "memory");
}
__device__ __forceinline__ void csync() { carr(); cwait(); }

__device__ __forceinline__ float fast_tanh(float x) {
    return 1.f - __fdividef(2.f, __expf(2.f*x) + 1.f);
}

// ---------------------------------------------------------------------------
// prep: composed weights. W layout [rank][k][c][q]; bias layout [rank][c][q].
// gate (q, c) of CTA rank j <-> global gate row g = q*256 + j*32 + c
// ---------------------------------------------------------------------------
__global__ void prep_kernel(const float* __restrict__ W, const float* __restrict__ R,
                            const float* __restrict__ b, const float* __restrict__ b_in,
                            const float* __restrict__ W_in)
{
    int idx = blockIdx.x * blockDim.x + threadIdx.x;
    if (idx < CL*HH*LCOLS) {
        int q = idx & 3;
        int c = (idx >> 2) & 31;
        int k = (idx >> 7) & 255;
        int j = idx >> 15;
        int g = q*256 + j*32 + c;
        g_WT[idx] = W[(size_t)g*512 + 256 + k] + R[(size_t)g*256 + k];
    }
    if (idx < CL*IDIM*LCOLS) {
        int q = idx & 3;
        int c = (idx >> 2) & 31;
        int i = (idx >> 7) & 31;
        int j = idx >> 12;
        int g = q*256 + j*32 + c;
        float s = 0.f;
        for (int h = 0; h < HH; ++h) s += W[(size_t)g*512 + h] * W_in[(size_t)h*IDIM + i];
        g_WC[idx] = s;
    }
    if (idx < CL*LCOLS) {
        int q = idx & 3;
        int c = (idx >> 2) & 31;
        int j = idx >> 7;
        int g = q*256 + j*32 + c;
        float s = b[g];
        for (int h = 0; h < HH; ++h) s += W[(size_t)g*512 + h] * b_in[h];
        g_bc[idx] = s;
    }
}

// no-op pads so ncu's profiled launch (index 3) is recur_kernel
__global__ void dummy_kernel() {}

// ---------------------------------------------------------------------------
// Recurrence: 16 clusters x 8 CTAs, 512 thr/CTA (16 warps).
// Lane split: kh = (lane>>4) picks k-half [0,144) / [144,288); both halves run
// the same instruction stream (x rows stored contiguously after h rows).
// Thread: c = (warp&1)*16 + (lane&15); rows r0 = (tid>>6)*4.
// After GEMM: SHFL.BFLY(16) + f32x2 add combines the halves; all lanes then
// run the pointwise cell (kh=1 lanes are shadow copies); kh=0 lanes broadcast.
// ---------------------------------------------------------------------------
__global__ void __cluster_dims__(CL, 1, 1) __launch_bounds__(NTHR, 1)
recur_kernel(const float* __restrict__ x)
{
    extern __shared__ float sm[];
    float* W_s  = sm;                    // [k(0..287)][c(0..31)][q(0..3)]
    float* AB   = sm + W_S_F;            // 2 x [k(0..287)][row(0..31)]
    float* bc2  = AB + AB_F;             // [kh(2)][c][q] (kh=1 zeros)

    unsigned rank; asm("mov.u32 %0, %%cluster_ctarank;" : "=r"(rank));
    const int cid = blockIdx.x >> 3;     // cluster id (0..15)
    const int b0  = cid * ROWS;
    const int tid = threadIdx.x;
    const int lane = tid & 31;
    const int kh  = lane >> 4;           // k-half
    const int c   = ((tid >> 5) & 1)*16 + (lane & 15);  // local hidden unit
    const int r0  = (tid >> 6) * 4;      // 4 rows per thread
    const int hid = rank * 32 + c;       // global hidden unit

    // Load resident weights; zero AB0 h-rows; bias halves
    {
        const float4* wt = (const float4*)(g_WT + (size_t)rank*HH*LCOLS);
        float4* d = (float4*)W_s;
        for (int i = tid; i < (HH*LCOLS)/4; i += NTHR) d[i] = wt[i];
        const float4* wc = (const float4*)(g_WC + (size_t)rank*IDIM*LCOLS);
        float4* d2 = (float4*)(W_s + HH*LCOLS);
        for (int i = tid; i < (IDIM*LCOLS)/4; i += NTHR) d2[i] = wc[i];
        if (tid < LCOLS) { bc2[tid] = g_bc[rank*LCOLS + tid]; bc2[LCOLS + tid] = 0.f; }
        float4 z = make_float4(0.f,0.f,0.f,0.f);
        float4* hz = (float4*)AB;
        for (int i = tid; i < (HH*ROWS)/4; i += NTHR) hz[i] = z;   // h(t=0)=0
    }

    // x plumbing: thread -> (row = tid>>4, 2 features at (tid&15)*2)
    const int xr = tid >> 4;
    const int xi = (tid & 15) * 2;
    const float* xrowbase = x + (size_t)(b0 + xr)*SS*IDIM + xi;

    float2 px = *(const float2*)(xrowbase);            // t = 0
    AB[(HH + xi    )*ROWS + xr] = px.x;                // x rows live at k=256..287
    AB[(HH + xi + 1)*ROWS + xr] = px.y;
    csync();

    float cst[4], nst[4], mst[4], hn[4];
    #pragma unroll
    for (int r = 0; r < 4; ++r) { cst[r]=0.f; nst[r]=0.f; mst[r]=0.f; hn[r]=0.f; }

    // hoisted: bias packs (kh=1 lanes get zeros -> bias counted once after bfly)
    u64 bv[4];
    {
        float4 bb = *(const float4*)(bc2 + kh*LCOLS + c*4);
        bv[0]=pk2(bb.x,bb.x); bv[1]=pk2(bb.y,bb.y); bv[2]=pk2(bb.z,bb.z); bv[3]=pk2(bb.w,bb.w);
    }

    const unsigned ab_byte = s2u(sm) + (unsigned)W_S_F*4u;   // AB base (bytes)
    const float* wbase = W_s + kh*KHALF*LCOLS + c*4;
    const int    aoff  = kh*KHALF*ROWS + r0;

    int cur = 0;
    for (int t = 0; t < SS; ++t) {
        if (t + 1 < SS) px = *(const float2*)(xrowbase + (size_t)(t+1)*IDIM);

        // partial gates over this lane's k-half
        u64 acc0 = bv[0], acc1 = bv[0];   // q=0 rows(r0,r0+1),(r0+2,r0+3)
        u64 acc2 = bv[1], acc3 = bv[1];
        u64 acc4 = bv[2], acc5 = bv[2];
        u64 acc6 = bv[3], acc7 = bv[3];
        {
            const float* ap = AB + cur*ABH_F + aoff;
            const float* wp = wbase;
            #pragma unroll 6
            for (int k = 0; k < KHALF; ++k) {
                ulonglong2 a0 = *(const ulonglong2*)ap;     // 4 rows, 16B broadcast per half
                float4 w = *(const float4*)wp;              // 4 gate weights
                u64 w0 = pk2(w.x, w.x), w1 = pk2(w.y, w.y);
                u64 w2 = pk2(w.z, w.z), w3 = pk2(w.w, w.w);
                fma2(acc0, a0.x, w0); fma2(acc1, a0.y, w0);
                fma2(acc2, a0.x, w1); fma2(acc3, a0.y, w1);
                fma2(acc4, a0.x, w2); fma2(acc5, a0.y, w2);
                fma2(acc6, a0.x, w3); fma2(acc7, a0.y, w3);
                ap += ROWS; wp += LCOLS;
            }
        }

        // combine k-halves: butterfly over lane bit 4 (partner has same (c, r0))
        acc0 = add2(acc0, __shfl_xor_sync(0xffffffffu, acc0, 16));
        acc1 = add2(acc1, __shfl_xor_sync(0xffffffffu, acc1, 16));
        acc2 = add2(acc2, __shfl_xor_sync(0xffffffffu, acc2, 16));
        acc3 = add2(acc3, __shfl_xor_sync(0xffffffffu, acc3, 16));
        acc4 = add2(acc4, __shfl_xor_sync(0xffffffffu, acc4, 16));
        acc5 = add2(acc5, __shfl_xor_sync(0xffffffffu, acc5, 16));
        acc6 = add2(acc6, __shfl_xor_sync(0xffffffffu, acc6, 16));
        acc7 = add2(acc7, __shfl_xor_sync(0xffffffffu, acc7, 16));

        // pointwise sLSTM cell (all lanes; kh=1 lanes are shadow copies)
        float gi[4], gff[4], gz[4], go[4];
        upk2(gi[0],  gi[1],  acc0); upk2(gi[2],  gi[3],  acc1);
        upk2(gff[0], gff[1], acc2); upk2(gff[2], gff[3], acc3);
        upk2(gz[0],  gz[1],  acc4); upk2(gz[2],  gz[3],  acc5);
        upk2(go[0],  go[1],  acc6); upk2(go[2],  go[3],  acc7);
        #pragma unroll
        for (int r = 0; r < 4; ++r) {
            float iraw = gi[r], fraw = gff[r], zraw = gz[r], oraw = go[r];
            float lf  = -__logf(1.f + __expf(-fraw));   // log(sigmoid(f))
            float mn  = fmaxf(lf + mst[r], iraw);
            float ip  = __expf(iraw - mn);
            float fp  = __expf(lf + mst[r] - mn);
            float cn  = fp*cst[r] + ip*fast_tanh(zraw);
            float nn  = fp*nst[r] + ip;
            float so  = __fdividef(1.f, 1.f + __expf(-oraw));
            float hv  = so * fast_tanh(__fdividef(cn, nn));
            cst[r]=cn; nst[r]=nn; mst[r]=mn; hn[r]=hv;
        }

        int nxt = cur ^ 1;

        // kh=0 lanes broadcast h (4 rows x 1 hid, 16B) to all 8 CTAs' AB[nxt]
        if (kh == 0) {
            u64 hp0 = pk2(hn[0],hn[1]), hp1 = pk2(hn[2],hn[3]);
            unsigned dst = ab_byte + (unsigned)(nxt*ABH_F + hid*ROWS + r0)*4u;
            #pragma unroll
            for (unsigned tr = 0; tr < CL; ++tr)
                stc128(mapa_sh(dst, tr), hp0, hp1);
        }

        // stage x(t+1) into AB[nxt] x-rows
        if (t + 1 < SS) {
            float* xd = AB + nxt*ABH_F + HH*ROWS;
            xd[(xi    )*ROWS + xr] = px.x;
            xd[(xi + 1)*ROWS + xr] = px.y;
        }

        carr();     // release my stores
        cwait();    // acquire everyone's
        cur = nxt;
    }

    // final hidden state to GMEM
    if (kh == 0) {
        #pragma unroll
        for (int r = 0; r < 4; ++r)
            g_hfinal[(size_t)(b0 + r0 + r)*HH + hid] = hn[r];
    }
}

// ---------------------------------------------------------------------------
// Epilogue: out = h @ W_out^T + b_out, then layernorm over O=24
// ---------------------------------------------------------------------------
__global__ void __launch_bounds__(64) epi_kernel(const float* __restrict__ Wo,
                                                 const float* __restrict__ bo,
                                                 float* __restrict__ out)
{
    __shared__ float hrow[HH];
    __shared__ float ov[OO];
    __shared__ float s_mu, s_rs;
    int b = blockIdx.x, tid = threadIdx.x;

    const float4* hs = (const float4*)(g_hfinal + (size_t)b*HH);
    for (int i = tid; i < HH/4; i += 64) ((float4*)hrow)[i] = hs[i];
    __syncthreads();

    if (tid < OO) {
        float s = bo[tid];
        const float* w = Wo + (size_t)tid*HH;
        #pragma unroll 8
        for (int k = 0; k < HH; ++k) s += hrow[k]*w[k];
        ov[tid] = s;
    }
    __syncthreads();
    if (tid == 0) {
        float mu = 0.f;
        for (int o = 0; o < OO; ++o) mu += ov[o];
        mu *= (1.f/OO);
        float va = 0.f;
        for (int o = 0; o < OO; ++o) { float d = ov[o]-mu; va += d*d; }
        va *= (1.f/OO);
        s_mu = mu; s_rs = rsqrtf(va + 1e-5f);
    }
    __syncthreads();
    if (tid < OO) out[(size_t)b*OO + tid] = (ov[tid]-s_mu)*s_rs;
}

// ---------------------------------------------------------------------------
extern "C" void kernel_launch(void* const* d_in, const int* in_sizes, int n_in,
                              void* d_out, int out_size)
{
    (void)in_sizes; (void)n_in; (void)out_size;
    const float* x     = (const float*)d_in[0];
    const float* W_in  = (const float*)d_in[1];
    const float* b_in  = (const float*)d_in[2];
    const float* W     = (const float*)d_in[3];
    const float* R     = (const float*)d_in[4];
    const float* b     = (const float*)d_in[5];
    const float* W_out = (const float*)d_in[6];
    const float* b_out = (const float*)d_in[7];
    float* out = (float*)d_out;

    cudaFuncSetAttribute(recur_kernel, cudaFuncAttributeMaxDynamicSharedMemorySize, SMEM_BYTES);

    prep_kernel<<<(CL*HH*LCOLS)/256, 256>>>(W, R, b, b_in, W_in);   // launch 0
    dummy_kernel<<<1, 32>>>();                                       // launch 1
    dummy_kernel<<<1, 32>>>();                                       // launch 2
    recur_kernel<<<GRID_R, NTHR, SMEM_BYTES>>>(x);                   // launch 3 (ncu lands here)
    epi_kernel<<<BB, 64>>>(W_out, b_out, out);                       // launch 4
}

// round 6
// speedup vs baseline: 1.5105x; 1.0003x over previous
#include <cuda_runtime.h>
#include <math.h>

// Problem constants
#define BB    512
#define SS    256
#define IDIM  32
#define HH    256
#define OO    24

// Recurrence kernel geometry
#define CL     8      // cluster size (CTAs per cluster)
#define ROWS   32     // batch rows per cluster
#define LCOLS  128    // gate columns per CTA (4 gates x 32 hidden)
#define NTHR   512    // threads per CTA (16 warps; in-warp k-split by 4)
#define KTOT   (HH+IDIM)          // 288 reduction rows (256 h + 32 x)
#define KQ     (KTOT/4)           // 72 per k-quarter
#define NCLU   (BB/ROWS)          // 16 clusters
#define GRID_R (NCLU*CL)          // 128 CTAs

// SMEM layout (floats)
#define W_S_F    (KTOT*LCOLS)     // 288*128 = 36864 : [k][c][q]
#define ABH_F    (KTOT*ROWS)      // 288*32 = 9216 : one activation buffer [k][row]
#define AB_F     (2*ABH_F)        // double buffered (h rows 0..255, x rows 256..287)
#define BC2_F    (2*LCOLS)        // bias [sel][c][q]; sel=1 half is zeros
#define SMEM_F   (W_S_F+AB_F+BC2_F)
#define SMEM_BYTES (SMEM_F*4)

// Device scratch (allocation-free rule: __device__ globals)
__device__ float g_WT[CL*HH*LCOLS];     // [rank][k][c][q] : (W[:,H:]+R) slice
__device__ float g_WC[CL*IDIM*LCOLS];   // [rank][i][c][q] : composed Wx@W_in slice
__device__ float g_bc[CL*LCOLS];        // composed bias [rank][c][q]
__device__ float g_hfinal[BB*HH];       // final hidden state

typedef unsigned long long u64;

__device__ __forceinline__ u64 pk2(float a, float b) {
    u64 r; asm("mov.b64 %0,{%1,%2};" : "=l"(r) : "f"(a), "f"(b)); return r;
}
__device__ __forceinline__ void upk2(float &a, float &b, u64 v) {
    asm("mov.b64 {%0,%1},%2;" : "=f"(a), "=f"(b) : "l"(v));
}
__device__ __forceinline__ void fma2(u64 &d, u64 a, u64 b) {
    asm("fma.rn.f32x2 %0,%1,%2,%0;" : "+l"(d) : "l"(a), "l"(b));
}
__device__ __forceinline__ u64 add2(u64 a, u64 b) {
    u64 r; asm("add.rn.f32x2 %0,%1,%2;" : "=l"(r) : "l"(a), "l"(b)); return r;
}
__device__ __forceinline__ unsigned mapa_sh(unsigned a, unsigned r) {
    unsigned o; asm("mapa.shared::cluster.u32 %0,%1,%2;" : "=r"(o) : "r"(a), "r"(r)); return o;
}
__device__ __forceinline__ void stc128(unsigned a, u64 v0, u64 v1) {
    asm volatile("st.shared::cluster.v2.b64 [%0],{%1,%2};" :: "r"(a), "l"(v0), "l"(v1) : "memory");
}
__device__ __forceinline__ unsigned s2u(const void *p) {
    unsigned r;
    asm("{.reg .u64 t; cvta.to.shared.u64 t,%1; cvt.u32.u64 %0,t;}" : "=r"(r) : "l"(p));
    return r;
}
__device__ __forceinline__ void carr() {
    asm volatile("barrier.cluster.arrive.aligned;" ::: "memory");
}
__device__ __forceinline__ void cwait() {
    asm volatile("barrier.cluster.wait.aligned;" ::: "memory");
}
__device__ __forceinline__ void csync() { carr(); cwait(); }

__device__ __forceinline__ float fast_tanh(float x) {
    return 1.f - __fdividef(2.f, __expf(2.f*x) + 1.f);
}

// ---------------------------------------------------------------------------
// prep: composed weights. W layout [rank][k][c][q]; bias layout [rank][c][q].
// gate (q, c) of CTA rank j <-> global gate row g = q*256 + j*32 + c
// ---------------------------------------------------------------------------
__global__ void prep_kernel(const float* __restrict__ W, const float* __restrict__ R,
                            const float* __restrict__ b, const float* __restrict__ b_in,
                            const float* __restrict__ W_in)
{
    int idx = blockIdx.x * blockDim.x + threadIdx.x;
    if (idx < CL*HH*LCOLS) {
        int q = idx & 3;
        int c = (idx >> 2) & 31;
        int k = (idx >> 7) & 255;
        int j = idx >> 15;
        int g = q*256 + j*32 + c;
        g_WT[idx] = W[(size_t)g*512 + 256 + k] + R[(size_t)g*256 + k];
    }
    if (idx < CL*IDIM*LCOLS) {
        int q = idx & 3;
        int c = (idx >> 2) & 31;
        int i = (idx >> 7) & 31;
        int j = idx >> 12;
        int g = q*256 + j*32 + c;
        float s = 0.f;
        for (int h = 0; h < HH; ++h) s += W[(size_t)g*512 + h] * W_in[(size_t)h*IDIM + i];
        g_WC[idx] = s;
    }
    if (idx < CL*LCOLS) {
        int q = idx & 3;
        int c = (idx >> 2) & 31;
        int j = idx >> 7;
        int g = q*256 + j*32 + c;
        float s = b[g];
        for (int h = 0; h < HH; ++h) s += W[(size_t)g*512 + h] * b_in[h];
        g_bc[idx] = s;
    }
}

// no-op pads so ncu's profiled launch (index 3) is recur_kernel
__global__ void dummy_kernel() {}

// ---------------------------------------------------------------------------
// Recurrence: 16 clusters x 8 CTAs, 512 thr/CTA (16 warps).
// Warp w: cbit = w&3 (8 hidden units c = cbit*8+cl), rg = w>>2 (rows r0=rg*8..+8)
// Lane: kq = lane>>3 picks k-quarter [kq*72,(kq+1)*72), cl = lane&7.
// Each thread: 8 rows x 4 gates partial sums over its k-quarter (f32x2 FFMA).
// Then 2-stage SHFL.BFLY(8,16) full-reduce; lanes split pointwise by kqb=kq&1
// (4 rows each, kq>=2 lanes shadow); kq<2 lanes broadcast h via DSMEM.
// ---------------------------------------------------------------------------
__global__ void __cluster_dims__(CL, 1, 1) __launch_bounds__(NTHR, 1)
recur_kernel(const float* __restrict__ x)
{
    extern __shared__ float sm[];
    float* W_s  = sm;                    // [k(0..287)][c(0..31)][q(0..3)]
    float* AB   = sm + W_S_F;            // 2 x [k(0..287)][row(0..31)]
    float* bc2  = AB + AB_F;             // [sel(2)][c][q] (sel=1 zeros)

    unsigned rank; asm("mov.u32 %0, %%cluster_ctarank;" : "=r"(rank));
    const int cid = blockIdx.x >> 3;     // cluster id (0..15)
    const int b0  = cid * ROWS;
    const int tid = threadIdx.x;
    const int lane = tid & 31;
    const int warp = tid >> 5;
    const int kq   = lane >> 3;          // k-quarter
    const int kqb  = kq & 1;             // row-half ownership within the 8 rows
    const int cl   = lane & 7;
    const int c    = (warp & 3)*8 + cl;  // local hidden unit
    const int r0   = (warp >> 2) * 8;    // 8 rows per thread
    const int hid  = rank * 32 + c;      // global hidden unit

    // Load resident weights; zero AB0 h-rows; bias halves
    {
        const float4* wt = (const float4*)(g_WT + (size_t)rank*HH*LCOLS);
        float4* d = (float4*)W_s;
        for (int i = tid; i < (HH*LCOLS)/4; i += NTHR) d[i] = wt[i];
        const float4* wc = (const float4*)(g_WC + (size_t)rank*IDIM*LCOLS);
        float4* d2 = (float4*)(W_s + HH*LCOLS);
        for (int i = tid; i < (IDIM*LCOLS)/4; i += NTHR) d2[i] = wc[i];
        if (tid < LCOLS) { bc2[tid] = g_bc[rank*LCOLS + tid]; bc2[LCOLS + tid] = 0.f; }
        float4 z = make_float4(0.f,0.f,0.f,0.f);
        float4* hz = (float4*)AB;
        for (int i = tid; i < (HH*ROWS)/4; i += NTHR) hz[i] = z;   // h(t=0)=0
    }

    // x plumbing: thread -> (row = tid>>4, 2 features at (tid&15)*2)
    const int xr = tid >> 4;
    const int xi = (tid & 15) * 2;
    const float* xrowbase = x + (size_t)(b0 + xr)*SS*IDIM + xi;

    float2 px = *(const float2*)(xrowbase);            // t = 0
    AB[(HH + xi    )*ROWS + xr] = px.x;                // x rows live at k=256..287
    AB[(HH + xi + 1)*ROWS + xr] = px.y;
    csync();

    // states for the 4 owned rows: r0 + kqb*4 + {0..3}  (kq>=2 lanes shadow)
    float cst[4], nst[4], mst[4], hn[4];
    #pragma unroll
    for (int r = 0; r < 4; ++r) { cst[r]=0.f; nst[r]=0.f; mst[r]=0.f; hn[r]=0.f; }

    // bias packs: only kq==0 lanes carry real bias (counted once after reduce)
    u64 bv[4];
    {
        float4 bb = *(const float4*)(bc2 + (kq ? LCOLS : 0) + c*4);
        bv[0]=pk2(bb.x,bb.x); bv[1]=pk2(bb.y,bb.y); bv[2]=pk2(bb.z,bb.z); bv[3]=pk2(bb.w,bb.w);
    }

    const unsigned ab_byte = s2u(sm) + (unsigned)W_S_F*4u;   // AB base (bytes)
    const float* wbase = W_s + kq*KQ*LCOLS + c*4;
    const int    aoff  = kq*KQ*ROWS + r0;

    // hoisted remote store addresses (both double-buffer halves) for kq<2 lanes
    unsigned raA[CL], raB[CL];
    {
        unsigned d0 = ab_byte + (unsigned)(hid*ROWS + r0 + kqb*4)*4u;
        unsigned d1 = d0 + (unsigned)ABH_F*4u;
        #pragma unroll
        for (unsigned tr = 0; tr < CL; ++tr) { raA[tr] = mapa_sh(d0, tr); raB[tr] = mapa_sh(d1, tr); }
    }

    int cur = 0;
    for (int t = 0; t < SS; ++t) {
        // issue x(t+1) LDG early so its latency hides under the FMA block
        if (t + 1 < SS) px = *(const float2*)(xrowbase + (size_t)(t+1)*IDIM);

        // partial gates over this lane's k-quarter: 8 rows x 4 gates
        u64 acc[4][4];
        #pragma unroll
        for (int q = 0; q < 4; ++q) { acc[q][0]=bv[q]; acc[q][1]=bv[q]; acc[q][2]=bv[q]; acc[q][3]=bv[q]; }
        {
            const float* ap = AB + cur*ABH_F + aoff;
            const float* wp = wbase;
            #pragma unroll 8
            for (int k = 0; k < KQ; ++k) {
                ulonglong2 a01 = *(const ulonglong2*)ap;        // rows r0..r0+3
                ulonglong2 a23 = *(const ulonglong2*)(ap + 4);  // rows r0+4..r0+7
                float4 w = *(const float4*)wp;                  // 4 gate weights
                u64 w0 = pk2(w.x, w.x), w1 = pk2(w.y, w.y);
                u64 w2 = pk2(w.z, w.z), w3 = pk2(w.w, w.w);
                fma2(acc[0][0], a01.x, w0); fma2(acc[0][1], a01.y, w0);
                fma2(acc[0][2], a23.x, w0); fma2(acc[0][3], a23.y, w0);
                fma2(acc[1][0], a01.x, w1); fma2(acc[1][1], a01.y, w1);
                fma2(acc[1][2], a23.x, w1); fma2(acc[1][3], a23.y, w1);
                fma2(acc[2][0], a01.x, w2); fma2(acc[2][1], a01.y, w2);
                fma2(acc[2][2], a23.x, w2); fma2(acc[2][3], a23.y, w2);
                fma2(acc[3][0], a01.x, w3); fma2(acc[3][1], a01.y, w3);
                fma2(acc[3][2], a23.x, w3); fma2(acc[3][3], a23.y, w3);
                ap += ROWS; wp += LCOLS;
            }
        }

        // combine 4 k-quarters: butterfly over lane bits 3 and 4
        #pragma unroll
        for (int q = 0; q < 4; ++q) {
            #pragma unroll
            for (int p = 0; p < 4; ++p) {
                acc[q][p] = add2(acc[q][p], __shfl_xor_sync(0xffffffffu, acc[q][p], 8));
                acc[q][p] = add2(acc[q][p], __shfl_xor_sync(0xffffffffu, acc[q][p], 16));
            }
        }

        // lane picks its row-half: pairs (0,1) for kqb=0, (2,3) for kqb=1
        float gi[4], gff[4], gz[4], go[4];
        {
            u64 s0 = kqb ? acc[0][2] : acc[0][0], s1 = kqb ? acc[0][3] : acc[0][1];
            upk2(gi[0], gi[1], s0);  upk2(gi[2], gi[3], s1);
            s0 = kqb ? acc[1][2] : acc[1][0]; s1 = kqb ? acc[1][3] : acc[1][1];
            upk2(gff[0], gff[1], s0); upk2(gff[2], gff[3], s1);
            s0 = kqb ? acc[2][2] : acc[2][0]; s1 = kqb ? acc[2][3] : acc[2][1];
            upk2(gz[0], gz[1], s0);  upk2(gz[2], gz[3], s1);
            s0 = kqb ? acc[3][2] : acc[3][0]; s1 = kqb ? acc[3][3] : acc[3][1];
            upk2(go[0], go[1], s0);  upk2(go[2], go[3], s1);
        }

        // pointwise sLSTM cell (4 owned rows; kq>=2 lanes shadow kq<2)
        #pragma unroll
        for (int r = 0; r < 4; ++r) {
            float iraw = gi[r], fraw = gff[r], zraw = gz[r], oraw = go[r];
            float lf  = -__logf(1.f + __expf(-fraw));   // log(sigmoid(f))
            float mn  = fmaxf(lf + mst[r], iraw);
            float ip  = __expf(iraw - mn);
            float fp  = __expf(lf + mst[r] - mn);
            float cn  = fp*cst[r] + ip*fast_tanh(zraw);
            float nn  = fp*nst[r] + ip;
            float so  = __fdividef(1.f, 1.f + __expf(-oraw));
            float hv  = so * fast_tanh(__fdividef(cn, nn));
            cst[r]=cn; nst[r]=nn; mst[r]=mn; hn[r]=hv;
        }

        int nxt = cur ^ 1;

        // kq<2 lanes broadcast h (4 rows x 1 hid, 16B) to all 8 CTAs' AB[nxt]
        if (kq < 2) {
            u64 hp0 = pk2(hn[0],hn[1]), hp1 = pk2(hn[2],hn[3]);
            #pragma unroll
            for (unsigned tr = 0; tr < CL; ++tr)
                stc128(nxt ? raB[tr] : raA[tr], hp0, hp1);
        }

        // stage x(t+1) into AB[nxt] x-rows
        if (t + 1 < SS) {
            float* xd = AB + nxt*ABH_F + HH*ROWS;
            xd[(xi    )*ROWS + xr] = px.x;
            xd[(xi + 1)*ROWS + xr] = px.y;
        }

        carr();     // release my stores
        cwait();    // acquire everyone's
        cur = nxt;
    }

    // final hidden state to GMEM (owned rows only)
    if (kq < 2) {
        #pragma unroll
        for (int r = 0; r < 4; ++r)
            g_hfinal[(size_t)(b0 + r0 + kqb*4 + r)*HH + hid] = hn[r];
    }
}

// ---------------------------------------------------------------------------
// Epilogue: out = h @ W_out^T + b_out, then layernorm over O=24
// ---------------------------------------------------------------------------
__global__ void __launch_bounds__(64) epi_kernel(const float* __restrict__ Wo,
                                                 const float* __restrict__ bo,
                                                 float* __restrict__ out)
{
    __shared__ float hrow[HH];
    __shared__ float ov[OO];
    __shared__ float s_mu, s_rs;
    int b = blockIdx.x, tid = threadIdx.x;

    const float4* hs = (const float4*)(g_hfinal + (size_t)b*HH);
    for (int i = tid; i < HH/4; i += 64) ((float4*)hrow)[i] = hs[i];
    __syncthreads();

    if (tid < OO) {
        float s = bo[tid];
        const float* w = Wo + (size_t)tid*HH;
        #pragma unroll 8
        for (int k = 0; k < HH; ++k) s += hrow[k]*w[k];
        ov[tid] = s;
    }
    __syncthreads();
    if (tid == 0) {
        float mu = 0.f;
        for (int o = 0; o < OO; ++o) mu += ov[o];
        mu *= (1.f/OO);
        float va = 0.f;
        for (int o = 0; o < OO; ++o) { float d = ov[o]-mu; va += d*d; }
        va *= (1.f/OO);
        s_mu = mu; s_rs = rsqrtf(va + 1e-5f);
    }
    __syncthreads();
    if (tid < OO) out[(size_t)b*OO + tid] = (ov[tid]-s_mu)*s_rs;
}

// ---------------------------------------------------------------------------
extern "C" void kernel_launch(void* const* d_in, const int* in_sizes, int n_in,
                              void* d_out, int out_size)
{
    (void)in_sizes; (void)n_in; (void)out_size;
    const float* x     = (const float*)d_in[0];
    const float* W_in  = (const float*)d_in[1];
    const float* b_in  = (const float*)d_in[2];
    const float* W     = (const float*)d_in[3];
    const float* R     = (const float*)d_in[4];
    const float* b     = (const float*)d_in[5];
    const float* W_out = (const float*)d_in[6];
    const float* b_out = (const float*)d_in[7];
    float* out = (float*)d_out;

    cudaFuncSetAttribute(recur_kernel, cudaFuncAttributeMaxDynamicSharedMemorySize, SMEM_BYTES);

    prep_kernel<<<(CL*HH*LCOLS)/256, 256>>>(W, R, b, b_in, W_in);   // launch 0
    dummy_kernel<<<1, 32>>>();                                       // launch 1
    dummy_kernel<<<1, 32>>>();                                       // launch 2
    recur_kernel<<<GRID_R, NTHR, SMEM_BYTES>>>(x);                   // launch 3 (ncu lands here)
    epi_kernel<<<BB, 64>>>(W_out, b_out, out);                       // launch 4
}

// round 8
// speedup vs baseline: 2.6328x; 1.7430x over previous
#include <cuda_runtime.h>
#include <cuda_bf16.h>
#include <math.h>

// Problem constants
#define BB    512
#define SS    256
#define IDIM  32
#define HH    256
#define OO    24

// Geometry
#define CL     8                  // CTAs per cluster
#define ROWS   32                 // batch rows per cluster
#define NCLU   (BB/ROWS)          // 16 clusters
#define GRID_R (NCLU*CL)          // 128 CTAs
#define NTHR   512                // 16 warps
#define KTOT   288                // 256 h + 32 x
#define NCH    18                 // 18 k16 chunks

#define ASTRIDE 592               // bytes per k-row (288*2=576, padded: conflict-free ldmatrix)
#define A_BYTES (128*ASTRIDE)     // 75776 per precision
#define B_BYTES (32*ASTRIDE)      // 18944 per precision

// SMEM offsets (bytes)
#define A_HI   0
#define A_LO   75776
#define B_HI   151552
#define B_LO   170496
#define ACCO   189440             // float [128 m][36] (padded for float4 reads)
#define STGO   207872             // float [32 c][36]
#define SMEM_BYTES 212480

// Device scratch
__device__ __align__(16) unsigned char g_Ahi[CL*A_BYTES];
__device__ __align__(16) unsigned char g_Alo[CL*A_BYTES];
__device__ float g_bc[CL*128];    // composed bias [rank][c*4+q]
__device__ float g_hfinal[BB*HH];

typedef unsigned long long u64;

// ---------------- helpers ----------------
__device__ __forceinline__ unsigned s2u(const void *p) {
    unsigned r;
    asm("{.reg .u64 t; cvta.to.shared.u64 t,%1; cvt.u32.u64 %0,t;}" : "=r"(r) : "l"(p));
    return r;
}
__device__ __forceinline__ unsigned mapa_sh(unsigned a, unsigned r) {
    unsigned o; asm("mapa.shared::cluster.u32 %0,%1,%2;" : "=r"(o) : "r"(a), "r"(r)); return o;
}
__device__ __forceinline__ void stc64(unsigned a, u64 v) {
    asm volatile("st.shared::cluster.b64 [%0],%1;" :: "r"(a), "l"(v) : "memory");
}
__device__ __forceinline__ void carr() { asm volatile("barrier.cluster.arrive.aligned;" ::: "memory"); }
__device__ __forceinline__ void cwait(){ asm volatile("barrier.cluster.wait.aligned;"   ::: "memory"); }
__device__ __forceinline__ void csync(){ carr(); cwait(); }

__device__ __forceinline__ void ldm4(unsigned* r, unsigned a) {
    asm volatile("ldmatrix.sync.aligned.m8n8.x4.shared.b16 {%0,%1,%2,%3},[%4];"
        : "=r"(r[0]), "=r"(r[1]), "=r"(r[2]), "=r"(r[3]) : "r"(a));
}
__device__ __forceinline__ void mma16816(float* d, const unsigned* a, unsigned b0, unsigned b1) {
    asm volatile("mma.sync.aligned.m16n8k16.row.col.f32.bf16.bf16.f32 "
        "{%0,%1,%2,%3},{%4,%5,%6,%7},{%8,%9},{%0,%1,%2,%3};"
        : "+f"(d[0]), "+f"(d[1]), "+f"(d[2]), "+f"(d[3])
        : "r"(a[0]), "r"(a[1]), "r"(a[2]), "r"(a[3]), "r"(b0), "r"(b1));
}

__device__ __forceinline__ float fast_tanh(float x) {
    return 1.f - __fdividef(2.f, __expf(2.f*x) + 1.f);
}
__device__ __forceinline__ void split4(const float* v, u64 &vh, u64 &vl) {
    u64 H = 0, L = 0;
    #pragma unroll
    for (int j = 0; j < 4; ++j) {
        __nv_bfloat16 bh = __float2bfloat16(v[j]);
        float fh = __bfloat162float(bh);
        __nv_bfloat16 bl = __float2bfloat16(v[j] - fh);
        H |= (u64)__bfloat16_as_ushort(bh) << (16*j);
        L |= (u64)__bfloat16_as_ushort(bl) << (16*j);
    }
    vh = H; vl = L;
}

// ---------------------------------------------------------------------------
// prep: bf16 hi/lo weight images [rank][m][k], m = c*4+q <-> gate g = q*256+rank*32+c
// k<256: W[:,256:]+R ; 256..287: W[:, :256]@W_in ; pad 288..295 zero. Bias separate.
// ---------------------------------------------------------------------------
__global__ void prep_kernel(const float* __restrict__ W, const float* __restrict__ R,
                            const float* __restrict__ b, const float* __restrict__ b_in,
                            const float* __restrict__ W_in)
{
    int idx = blockIdx.x * blockDim.x + threadIdx.x;
    if (idx < CL*128*296) {
        int kk   = idx % 296;
        int m    = (idx / 296) % 128;
        int rank = idx / (296*128);
        int c = m >> 2, q = m & 3;
        int g = q*256 + rank*32 + c;
        float w = 0.f;
        if (kk < 256) {
            w = W[(size_t)g*512 + 256 + kk] + R[(size_t)g*256 + kk];
        } else if (kk < 288) {
            int i = kk - 256;
            float s = 0.f;
            for (int h = 0; h < HH; ++h) s += W[(size_t)g*512 + h] * W_in[(size_t)h*IDIM + i];
            w = s;
        }
        __nv_bfloat16 hi = __float2bfloat16(w);
        __nv_bfloat16 lo = __float2bfloat16(w - __bfloat162float(hi));
        size_t off = (size_t)rank*A_BYTES + (size_t)m*ASTRIDE + kk*2;
        *(__nv_bfloat16*)(g_Ahi + off) = hi;
        *(__nv_bfloat16*)(g_Alo + off) = lo;
    }
    if (idx < CL*128) {
        int m = idx & 127, rank = idx >> 7;
        int c = m >> 2, q = m & 3;
        int g = q*256 + rank*32 + c;
        float s = b[g];
        for (int h = 0; h < HH; ++h) s += W[(size_t)g*512 + h] * b_in[h];
        g_bc[idx] = s;
    }
}

__global__ void dummy_kernel() {}

// ---------------------------------------------------------------------------
// Recurrence: HMMA (mma.sync bf16 hi/lo 3-term) per step; cluster of 8 shares h.
// warps 0-3: GEMM (m-tile 32 each). warps 8-15: pointwise. warps 0-7: h-broadcast.
// ---------------------------------------------------------------------------
__global__ void __cluster_dims__(CL, 1, 1) __launch_bounds__(NTHR, 1)
recur_kernel(const float* __restrict__ x)
{
    extern __shared__ unsigned char smem[];
    const unsigned base = s2u(smem);
    float* accS = (float*)(smem + ACCO);
    float* stgS = (float*)(smem + STGO);

    unsigned rank; asm("mov.u32 %0, %%cluster_ctarank;" : "=r"(rank));
    const int cid  = blockIdx.x >> 3;
    const int b0   = cid * ROWS;
    const int tid  = threadIdx.x;
    const int lane = tid & 31;
    const int warp = tid >> 5;

    // ---- load resident A tiles, zero B ----
    {
        const float4* sa = (const float4*)(g_Ahi + (size_t)rank*A_BYTES);
        const float4* sb = (const float4*)(g_Alo + (size_t)rank*A_BYTES);
        float4* da = (float4*)(smem + A_HI);
        float4* db = (float4*)(smem + A_LO);
        for (int i = tid; i < A_BYTES/16; i += NTHR) { da[i] = sa[i]; db[i] = sb[i]; }
        float4 z = make_float4(0.f,0.f,0.f,0.f);
        float4* bz = (float4*)(smem + B_HI);
        for (int i = tid; i < (2*B_BYTES)/16; i += NTHR) bz[i] = z;
    }
    __syncthreads();

    // x plumbing: all 512 threads: (n = tid>>4, feature pair ip = tid&15)
    const int n  = tid >> 4;
    const int ip = tid & 15;
    const float* xrowbase = x + (size_t)(b0 + n)*SS*IDIM + ip*2;
    unsigned char* xpH = smem + B_HI + n*ASTRIDE + 512 + ip*4;   // k = 256 + ip*2
    unsigned char* xpL = smem + B_LO + n*ASTRIDE + 512 + ip*4;
    {
        float2 x0 = *(const float2*)(xrowbase);
        __nv_bfloat16 hx = __float2bfloat16(x0.x), hy = __float2bfloat16(x0.y);
        unsigned uH = (unsigned)__bfloat16_as_ushort(hx) | ((unsigned)__bfloat16_as_ushort(hy) << 16);
        __nv_bfloat16 lx = __float2bfloat16(x0.x - __bfloat162float(hx));
        __nv_bfloat16 ly = __float2bfloat16(x0.y - __bfloat162float(hy));
        unsigned uL = (unsigned)__bfloat16_as_ushort(lx) | ((unsigned)__bfloat16_as_ushort(ly) << 16);
        *(unsigned*)xpH = uH; *(unsigned*)xpL = uL;
    }
    __syncthreads();
    csync();                       // B(0) ready cluster-wide

    // GEMM lane addresses (warps 0-3)
    const unsigned aH = base + A_HI + (unsigned)(warp*32 + (lane & 15))*ASTRIDE + (lane >> 4)*16;
    const unsigned aL = aH + (A_LO - A_HI);
    const unsigned bHa = base + B_HI + (unsigned)lane*ASTRIDE;
    const unsigned bLa = bHa + (B_LO - B_HI);

    // pointwise mapping (warps 8-15): c = ptid>>3, rq = ptid&7
    const int ptid = tid & 255;
    const int pc   = ptid >> 3;
    const int pr0  = (ptid & 7) * 4;
    float4 bias4 = ((const float4*)g_bc)[rank*32 + pc];
    float cst[4], nst[4], mst[4];
    #pragma unroll
    for (int r = 0; r < 4; ++r) { cst[r]=0.f; nst[r]=0.f; mst[r]=0.f; }

    // broadcast mapping (warps 0-7): nb = tid>>3, hqb = tid&7
    const int nb  = tid >> 3;
    const int hqb = tid & 7;
    unsigned raH[CL], raL[CL];
    {
        unsigned ho = (unsigned)nb*ASTRIDE + (rank*32 + hqb*4)*2;
        #pragma unroll
        for (unsigned r = 0; r < CL; ++r) {
            raH[r] = mapa_sh(base + B_HI + ho, r);
            raL[r] = mapa_sh(base + B_LO + ho, r);
        }
    }

    for (int t = 0; t < SS; ++t) {
        // ---- GEMM (warps 0-3): 32m x 32n x 288k, 3-term hi/lo ----
        if (warp < 4) {
            float d[2][4][4];
            #pragma unroll
            for (int mi = 0; mi < 2; ++mi)
                #pragma unroll
                for (int nj = 0; nj < 4; ++nj)
                    #pragma unroll
                    for (int e = 0; e < 4; ++e) d[mi][nj][e] = 0.f;

            #pragma unroll 6
            for (int ch = 0; ch < NCH; ++ch) {
                unsigned ka = ch*32;
                unsigned AH0[4], AH1[4], AL0[4], AL1[4], BHp[4], BHq[4], BLp[4], BLq[4];
                ldm4(AH0, aH + ka); ldm4(AH1, aH + 16*ASTRIDE + ka);
                ldm4(AL0, aL + ka); ldm4(AL1, aL + 16*ASTRIDE + ka);
                ldm4(BHp, bHa + ka); ldm4(BHq, bHa + ka + 16);
                ldm4(BLp, bLa + ka); ldm4(BLq, bLa + ka + 16);
                #pragma unroll
                for (int nj = 0; nj < 4; ++nj) {
                    mma16816(d[0][nj], AH0, BHp[nj], BHq[nj]);
                    mma16816(d[0][nj], AL0, BHp[nj], BHq[nj]);
                    mma16816(d[0][nj], AH0, BLp[nj], BLq[nj]);
                    mma16816(d[1][nj], AH1, BHp[nj], BHq[nj]);
                    mma16816(d[1][nj], AL1, BHp[nj], BHq[nj]);
                    mma16816(d[1][nj], AH1, BLp[nj], BLq[nj]);
                }
            }
            // fragment store: acc[m][36] (row = gate m, col = batch row)
            #pragma unroll
            for (int mi = 0; mi < 2; ++mi) {
                int row = warp*32 + mi*16 + (lane >> 2);
                #pragma unroll
                for (int nj = 0; nj < 4; ++nj) {
                    int col = nj*8 + (lane & 3)*2;
                    *(float2*)(accS + row*36 + col)     = make_float2(d[mi][nj][0], d[mi][nj][1]);
                    *(float2*)(accS + (row+8)*36 + col) = make_float2(d[mi][nj][2], d[mi][nj][3]);
                }
            }
        }

        // prefetch x(t+1)
        float2 xv = make_float2(0.f, 0.f);
        if (t + 1 < SS) xv = *(const float2*)(xrowbase + (size_t)(t+1)*IDIM);

        __syncthreads();           // acc ready; local CTA done reading B(t)
        carr();                    // signal done-reading-B(t); wait later

        // ---- pointwise (warps 8-15): cell (pc, rows pr0..pr0+3) ----
        if (tid >= 256) {
            float4 g0 = *(const float4*)(accS + (pc*4+0)*36 + pr0);
            float4 g1 = *(const float4*)(accS + (pc*4+1)*36 + pr0);
            float4 g2 = *(const float4*)(accS + (pc*4+2)*36 + pr0);
            float4 g3 = *(const float4*)(accS + (pc*4+3)*36 + pr0);
            float gi[4] = {g0.x+bias4.x, g0.y+bias4.x, g0.z+bias4.x, g0.w+bias4.x};
            float gf[4] = {g1.x+bias4.y, g1.y+bias4.y, g1.z+bias4.y, g1.w+bias4.y};
            float gz[4] = {g2.x+bias4.z, g2.y+bias4.z, g2.z+bias4.z, g2.w+bias4.z};
            float go[4] = {g3.x+bias4.w, g3.y+bias4.w, g3.z+bias4.w, g3.w+bias4.w};
            float hv[4];
            #pragma unroll
            for (int r = 0; r < 4; ++r) {
                float lf  = -__logf(1.f + __expf(-gf[r]));
                float mn  = fmaxf(lf + mst[r], gi[r]);
                float ipr = __expf(gi[r] - mn);
                float fp  = __expf(lf + mst[r] - mn);
                float cn  = fp*cst[r] + ipr*fast_tanh(gz[r]);
                float nn  = fp*nst[r] + ipr;
                float so  = __fdividef(1.f, 1.f + __expf(-go[r]));
                hv[r] = so * fast_tanh(__fdividef(cn, nn));
                cst[r]=cn; nst[r]=nn; mst[r]=mn;
            }
            *(float4*)(stgS + pc*36 + pr0) = make_float4(hv[0], hv[1], hv[2], hv[3]);
            if (t == SS-1) {
                #pragma unroll
                for (int r = 0; r < 4; ++r)
                    g_hfinal[(size_t)(b0 + pr0 + r)*HH + rank*32 + pc] = hv[r];
            }
        }

        __syncthreads();           // stg ready
        cwait();                   // all CTAs done reading B(t)

        if (t + 1 < SS) {
            // x(t+1) (all threads)
            {
                __nv_bfloat16 hx = __float2bfloat16(xv.x), hy = __float2bfloat16(xv.y);
                unsigned uH = (unsigned)__bfloat16_as_ushort(hx) | ((unsigned)__bfloat16_as_ushort(hy) << 16);
                __nv_bfloat16 lx = __float2bfloat16(xv.x - __bfloat162float(hx));
                __nv_bfloat16 ly = __float2bfloat16(xv.y - __bfloat162float(hy));
                unsigned uL = (unsigned)__bfloat16_as_ushort(lx) | ((unsigned)__bfloat16_as_ushort(ly) << 16);
                *(unsigned*)xpH = uH; *(unsigned*)xpL = uL;
            }
            // h broadcast (warps 0-7): (nb, 4 hids hqb*4..+3) -> 8B hi + 8B lo x 8 CTAs
            if (tid < 256) {
                float v[4];
                #pragma unroll
                for (int j = 0; j < 4; ++j) v[j] = stgS[(hqb*4 + j)*36 + nb];
                u64 vH, vL; split4(v, vH, vL);
                #pragma unroll
                for (unsigned r = 0; r < CL; ++r) { stc64(raH[r], vH); stc64(raL[r], vL); }
            }
            carr(); cwait();       // B(t+1) ready cluster-wide
        }
    }
}

// ---------------------------------------------------------------------------
// Epilogue: out = h @ W_out^T + b_out, then layernorm over O=24
// ---------------------------------------------------------------------------
__global__ void __launch_bounds__(64) epi_kernel(const float* __restrict__ Wo,
                                                 const float* __restrict__ bo,
                                                 float* __restrict__ out)
{
    __shared__ float hrow[HH];
    __shared__ float ov[OO];
    __shared__ float s_mu, s_rs;
    int b = blockIdx.x, tid = threadIdx.x;

    const float4* hs = (const float4*)(g_hfinal + (size_t)b*HH);
    for (int i = tid; i < HH/4; i += 64) ((float4*)hrow)[i] = hs[i];
    __syncthreads();

    if (tid < OO) {
        float s = bo[tid];
        const float* w = Wo + (size_t)tid*HH;
        #pragma unroll 8
        for (int k = 0; k < HH; ++k) s += hrow[k]*w[k];
        ov[tid] = s;
    }
    __syncthreads();
    if (tid == 0) {
        float mu = 0.f;
        for (int o = 0; o < OO; ++o) mu += ov[o];
        mu *= (1.f/OO);
        float va = 0.f;
        for (int o = 0; o < OO; ++o) { float d = ov[o]-mu; va += d*d; }
        va *= (1.f/OO);
        s_mu = mu; s_rs = rsqrtf(va + 1e-5f);
    }
    __syncthreads();
    if (tid < OO) out[(size_t)b*OO + tid] = (ov[tid]-s_mu)*s_rs;
}

// ---------------------------------------------------------------------------
extern "C" void kernel_launch(void* const* d_in, const int* in_sizes, int n_in,
                              void* d_out, int out_size)
{
    (void)in_sizes; (void)n_in; (void)out_size;
    const float* x     = (const float*)d_in[0];
    const float* W_in  = (const float*)d_in[1];
    const float* b_in  = (const float*)d_in[2];
    const float* W     = (const float*)d_in[3];
    const float* R     = (const float*)d_in[4];
    const float* b     = (const float*)d_in[5];
    const float* W_out = (const float*)d_in[6];
    const float* b_out = (const float*)d_in[7];
    float* out = (float*)d_out;

    cudaFuncSetAttribute(recur_kernel, cudaFuncAttributeMaxDynamicSharedMemorySize, SMEM_BYTES);

    prep_kernel<<<(CL*128*296 + 255)/256, 256>>>(W, R, b, b_in, W_in);  // launch 0
    dummy_kernel<<<1, 32>>>();                                           // launch 1
    dummy_kernel<<<1, 32>>>();                                           // launch 2
    recur_kernel<<<GRID_R, NTHR, SMEM_BYTES>>>(x);                       // launch 3 (ncu)
    epi_kernel<<<BB, 64>>>(W_out, b_out, out);                           // launch 4
}